// round 12
// baseline (speedup 1.0000x reference)
#include <cuda_runtime.h>
#include <cuda_bf16.h>
#include <math.h>
#include <stdint.h>

#define BQ 8
#define CC 1024
#define DD 512
#define MROWS 32768            // B*N = 16*2048
#define EPSF 1e-6f

// ---- scratch (device globals; no allocation allowed) ----
__device__ float g_residual[(size_t)MROWS * DD];   // 64 MB fp32 residual
__device__ uint4 g_res_h4[(size_t)MROWS * 64];     // 32 MB bf16 hi  [row][512]
__device__ uint4 g_cb_h4[(size_t)BQ * CC * 64];    // 8 MB bf16 hi codebooks
__device__ float g_cbsq[BQ * CC];
__device__ float g_nl[MROWS];                      // per-row lo-norm
__device__ float g_zz[MROWS];                      // per-row ||r||^2
__device__ int   g_cmaxi[BQ];                      // max csq per codebook (bits)
__device__ int   g_nlcmaxi[BQ];                    // max lo-norm^2 per codebook
__device__ uint4 g_cand[(size_t)MROWS * 16];       // per row: 8 contribs x 2 uint4
__device__ int   g_queue[MROWS];                   // deferred (slow-path) rows
__device__ int   g_qcnt;                           // queue put counter
__device__ int   g_qtake;                          // queue take counter
__device__ float g_loss[BQ];

// ============================================================================
// portable PTX helpers
// ============================================================================
__device__ __forceinline__ uint32_t smem_to_u32(const void* p) {
    uint32_t a;
    asm("{ .reg .u64 t; cvta.to.shared.u64 t, %1; cvt.u32.u64 %0, t; }"
        : "=r"(a) : "l"(p));
    return a;
}
__device__ __forceinline__ void cpasync16(uint32_t dst, const void* src) {
    asm volatile("cp.async.cg.shared.global [%0], [%1], 16;" :: "r"(dst), "l"(src));
}
#define CP_COMMIT() asm volatile("cp.async.commit_group;" ::: "memory")
#define CP_WAIT(n)  asm volatile("cp.async.wait_group %0;" :: "n"(n) : "memory")

__device__ __forceinline__ void ldsm4(uint32_t& r0, uint32_t& r1, uint32_t& r2,
                                      uint32_t& r3, uint32_t addr) {
    asm volatile("ldmatrix.sync.aligned.m8n8.x4.shared.b16 {%0,%1,%2,%3}, [%4];"
                 : "=r"(r0), "=r"(r1), "=r"(r2), "=r"(r3) : "r"(addr));
}
__device__ __forceinline__ void mma16816(float* c, uint32_t a0, uint32_t a1,
                                         uint32_t a2, uint32_t a3,
                                         uint32_t b0, uint32_t b1) {
    asm volatile(
        "mma.sync.aligned.m16n8k16.row.col.f32.bf16.bf16.f32 "
        "{%0,%1,%2,%3}, {%4,%5,%6,%7}, {%8,%9}, {%0,%1,%2,%3};"
        : "+f"(c[0]), "+f"(c[1]), "+f"(c[2]), "+f"(c[3])
        : "r"(a0), "r"(a1), "r"(a2), "r"(a3), "r"(b0), "r"(b1));
}

__device__ __forceinline__ ushort4 hi4(float4 v) {
    ushort4 h;
    h.x = __bfloat16_as_ushort(__float2bfloat16_rn(v.x));
    h.y = __bfloat16_as_ushort(__float2bfloat16_rn(v.y));
    h.z = __bfloat16_as_ushort(__float2bfloat16_rn(v.z));
    h.w = __bfloat16_as_ushort(__float2bfloat16_rn(v.w));
    return h;
}
__device__ __forceinline__ float losq4(float4 v, ushort4 h) {
    float dx = v.x - __bfloat162float(__ushort_as_bfloat16(h.x));
    float dy = v.y - __bfloat162float(__ushort_as_bfloat16(h.y));
    float dz = v.z - __bfloat162float(__ushort_as_bfloat16(h.z));
    float dw = v.w - __bfloat162float(__ushort_as_bfloat16(h.w));
    return dx*dx + dy*dy + dz*dz + dw*dw;
}

// top-3 + 4th-value sentinel insert (cheap chain — keeps dist at the MMA floor)
__device__ __forceinline__ void ins4(float& v1, int& i1, float& v2, int& i2,
                                     float& v3, int& i3, float& v4,
                                     float v, int n) {
    if (v < v4) {
        if (v < v1)      { v4 = v3; v3 = v2; i3 = i2; v2 = v1; i2 = i1; v1 = v; i1 = n; }
        else if (v < v2) { v4 = v3; v3 = v2; i3 = i2; v2 = v; i2 = n; }
        else if (v < v3) { v4 = v3; v3 = v; i3 = n; }
        else             { v4 = v; }
    }
}

// ---------------------------------------------------------------------------
// rotation + residual update, shared by rotate (fast) and fixup (slow) paths
// ---------------------------------------------------------------------------
__device__ __forceinline__ void do_rotation(
    const float* __restrict__ cbs, const float* __restrict__ x, int qi,
    float* __restrict__ out_q, float* __restrict__ out_if,
    int writeIdx, int writeLoss, int writeConv,
    int row, int lane, int idx, float zz, float nz,
    const float4* zv_in, bool haveZ)
{
    float* zp = g_residual + (size_t)row * DD;
    const float4* zp4 = (const float4*)zp;
    const float* csq = g_cbsq + qi * CC;
    const float4* qp4 = (const float4*)(cbs + ((size_t)qi * CC + idx) * DD);
    float4 zv[4], qv[4];
    if (haveZ) {
#pragma unroll
        for (int j = 0; j < 4; j++) { zv[j] = zv_in[j]; qv[j] = qp4[lane + 32 * j]; }
    } else {
#pragma unroll
        for (int j = 0; j < 4; j++) { zv[j] = zp4[lane + 32 * j]; qv[j] = qp4[lane + 32 * j]; }
    }
    float zq = 0.f;
#pragma unroll
    for (int j = 0; j < 4; j++)
        zq += zv[j].x*qv[j].x + zv[j].y*qv[j].y + zv[j].z*qv[j].z + zv[j].w*qv[j].w;
#pragma unroll
    for (int o = 16; o; o >>= 1) zq += __shfl_xor_sync(0xFFFFFFFFu, zq, o);

    float qq = csq[idx];
    float ll = zz - 2.f * zq + qq;

    float nq = sqrtf(qq);
    float iz = 1.f / (nz + EPSF), iq = 1.f / (nq + EPSF);
    float s2 = zz * iz * iz + 2.f * zq * iz * iq + qq * iq * iq;
    float A2 = 2.f * (zz * iz + zq * iq) / s2;
    float Bc = 2.f * zz * iz * iq;
    float cz = 1.f - A2 * iz;
    float cq = Bc - A2 * iq;
    float sc = nq * iz;

    if (writeConv) {
        ushort4* rh = (ushort4*)g_res_h4;
        float nls = 0.f, zz2 = 0.f;
#pragma unroll
        for (int j = 0; j < 4; j++) {
            float4 z = zv[j], q = qv[j], t, r;
            t.x = (z.x * cz + q.x * cq) * sc;
            t.y = (z.y * cz + q.y * cq) * sc;
            t.z = (z.z * cz + q.z * cq) * sc;
            t.w = (z.w * cz + q.w * cq) * sc;
            r.x = z.x - t.x; r.y = z.y - t.y; r.z = z.z - t.z; r.w = z.w - t.w;
            ((float4*)zp)[lane + 32 * j] = r;
            ushort4 h = hi4(r);
            rh[(size_t)row * 128 + lane + 32 * j] = h;
            nls += losq4(r, h);
            zz2 += r.x*r.x + r.y*r.y + r.z*r.z + r.w*r.w;
        }
#pragma unroll
        for (int o = 16; o; o >>= 1) {
            nls += __shfl_xor_sync(0xFFFFFFFFu, nls, o);
            zz2 += __shfl_xor_sync(0xFFFFFFFFu, zz2, o);
        }
        if (lane == 0) { g_nl[row] = sqrtf(nls); g_zz[row] = zz2; }
    } else {
        const float4* xp4 = (const float4*)(x + (size_t)row * DD);
        float4* op4 = (float4*)(out_q + (size_t)row * DD);
#pragma unroll
        for (int j = 0; j < 4; j++) {
            float4 z = zv[j], q = qv[j], t, r, xv;
            t.x = (z.x * cz + q.x * cq) * sc;
            t.y = (z.y * cz + q.y * cq) * sc;
            t.z = (z.z * cz + q.z * cq) * sc;
            t.w = (z.w * cz + q.w * cq) * sc;
            r.x = z.x - t.x; r.y = z.y - t.y; r.z = z.z - t.z; r.w = z.w - t.w;
            xv = xp4[lane + 32 * j];
            op4[lane + 32 * j] = make_float4(xv.x - r.x, xv.y - r.y,
                                             xv.z - r.z, xv.w - r.w);
        }
    }

    if (writeIdx && lane == 0)
        out_if[(size_t)row * BQ + qi] = (float)idx;
    if (writeLoss && lane == 0)
        atomicAdd(&g_loss[qi], ll);
}

// ---------------------------------------------------------------------------
// init: residual = x (fp32 + bf16 hi), zz + nl per row, reset loss/cmax.
// ---------------------------------------------------------------------------
__global__ void init_kernel(const float* __restrict__ x) {
    int row  = blockIdx.x * 8 + (threadIdx.x >> 5);
    int lane = threadIdx.x & 31;
    const float4* xp = (const float4*)(x + (size_t)row * DD);
    float4* rp = (float4*)(g_residual + (size_t)row * DD);
    ushort4* rh = (ushort4*)g_res_h4;
    float nls = 0.f, zz = 0.f;
#pragma unroll
    for (int j = 0; j < 4; j++) {
        float4 v = xp[lane + 32 * j];
        rp[lane + 32 * j] = v;
        ushort4 h = hi4(v);
        rh[(size_t)row * 128 + lane + 32 * j] = h;
        nls += losq4(v, h);
        zz += v.x*v.x + v.y*v.y + v.z*v.z + v.w*v.w;
    }
#pragma unroll
    for (int o = 16; o; o >>= 1) {
        nls += __shfl_xor_sync(0xFFFFFFFFu, nls, o);
        zz  += __shfl_xor_sync(0xFFFFFFFFu, zz, o);
    }
    if (lane == 0) { g_nl[row] = sqrtf(nls); g_zz[row] = zz; }
    if (blockIdx.x == 0 && threadIdx.x < BQ) {
        g_loss[threadIdx.x] = 0.f;
        g_cmaxi[threadIdx.x] = 0;
        g_nlcmaxi[threadIdx.x] = 0;
    }
}

// ---------------------------------------------------------------------------
// codebook: cb_sq + bf16 hi + per-codebook max csq and max lo-norm^2
// ---------------------------------------------------------------------------
__global__ void cbsq_kernel(const float* __restrict__ cb) {
    int row  = blockIdx.x * 8 + (threadIdx.x >> 5);
    int lane = threadIdx.x & 31;
    const float4* p = (const float4*)(cb + (size_t)row * DD);
    ushort4* ch = (ushort4*)g_cb_h4;
    float s = 0.f, lsq = 0.f;
#pragma unroll
    for (int j = 0; j < 4; j++) {
        float4 v = p[lane + 32 * j];
        s += v.x * v.x + v.y * v.y + v.z * v.z + v.w * v.w;
        ushort4 h = hi4(v);
        ch[(size_t)row * 128 + lane + 32 * j] = h;
        lsq += losq4(v, h);
    }
#pragma unroll
    for (int o = 16; o; o >>= 1) {
        s += __shfl_xor_sync(0xFFFFFFFFu, s, o);
        lsq += __shfl_xor_sync(0xFFFFFFFFu, lsq, o);
    }
    if (lane == 0) {
        g_cbsq[row] = s;
        atomicMax(&g_cmaxi[row >> 10], __float_as_int(s));
        atomicMax(&g_nlcmaxi[row >> 10], __float_as_int(lsq));
    }
}

// ---------------------------------------------------------------------------
// hh-only distance GEMM (K=512 bf16), per-thread top-3 + v4 candidate lists.
// (floor-proven R8 configuration + queue-counter reset)
// ---------------------------------------------------------------------------
#define PITCH   80
#define TILEB   (128 * PITCH)
#define STAGEB  (2 * TILEB)
#define NKC     16
#define SMEM_DYN (4 * STAGEB)

__device__ __forceinline__ void issue_chunk(
    uint32_t sb, int rowBase, int qi, int nt, int kc, int stage)
{
    int koff = kc * 64;
    uint32_t base = sb + stage * STAGEB;
    int tid = threadIdx.x;
    size_t bRow = (size_t)(qi * CC + nt * 128);
#pragma unroll
    for (int i = 0; i < 2; i++) {
        int g = tid + 256 * i;
        int r = g >> 2, c = g & 3;
        cpasync16(base + r * PITCH + c * 16,
                  (const char*)g_res_h4 + (size_t)(rowBase + r) * 1024 + koff + c * 16);
        cpasync16(base + TILEB + r * PITCH + c * 16,
                  (const char*)g_cb_h4 + (bRow + r) * 1024 + koff + c * 16);
    }
}

__global__ __launch_bounds__(256, 2) void dist_mma_kernel(int qi)
{
    extern __shared__ char smem[];
    uint32_t sb = smem_to_u32(smem);

    const int tid  = threadIdx.x;
    const int wid  = tid >> 5;
    const int lane = tid & 31;
    const int rowBase = blockIdx.x * 128;
    const int wM = (wid & 3) * 32;
    const int wN = (wid >> 2) * 64;

    if (tid == 0) { g_qcnt = 0; g_qtake = 0; }   // idempotent reset before rotate

    const int aRow = lane & 15;
    const int aCol = (lane >> 4) * 16;
    const int bRowL = (lane & 7) + ((lane >> 4) << 3);
    const int bColL = ((lane >> 3) & 1) * 16;
    const uint32_t aOffBase = (uint32_t)((wM + aRow) * PITCH + aCol);
    const uint32_t bOffBase = (uint32_t)(TILEB + (wN + bRowL) * PITCH + bColL);

    const float2* csq2 = (const float2*)(g_cbsq + qi * CC);

    float cv1[4], cv2[4], cv3[4], cv4[4];
    int   ci1[4], ci2[4], ci3[4];
#pragma unroll
    for (int s = 0; s < 4; s++) {
        cv1[s] = INFINITY; cv2[s] = INFINITY; cv3[s] = INFINITY; cv4[s] = INFINITY;
        ci1[s] = 0x7fffffff; ci2[s] = 0x7fffffff; ci3[s] = 0x7fffffff;
    }

#pragma unroll 1
    for (int nt = 0; nt < 8; nt++) {
        float acc[2][8][4];
#pragma unroll
        for (int mf = 0; mf < 2; mf++)
#pragma unroll
            for (int nf = 0; nf < 8; nf++)
#pragma unroll
                for (int e = 0; e < 4; e++) acc[mf][nf][e] = 0.f;

        issue_chunk(sb, rowBase, qi, nt, 0, 0); CP_COMMIT();
        issue_chunk(sb, rowBase, qi, nt, 1, 1); CP_COMMIT();
        issue_chunk(sb, rowBase, qi, nt, 2, 2); CP_COMMIT();

#pragma unroll 1
        for (int kc = 0; kc < NKC; kc++) {
            if (kc < NKC - 2) { CP_WAIT(2); } else if (kc == NKC - 2) { CP_WAIT(1); }
            else { CP_WAIT(0); }
            __syncthreads();
            if (kc + 3 < NKC) {
                issue_chunk(sb, rowBase, qi, nt, kc + 3, (kc + 3) & 3);
                CP_COMMIT();
            }

            uint32_t stageBase = sb + (kc & 3) * STAGEB;
#pragma unroll
            for (int k16 = 0; k16 < 2; k16++) {
                uint32_t a[2][4];
#pragma unroll
                for (int mf = 0; mf < 2; mf++)
                    ldsm4(a[mf][0], a[mf][1], a[mf][2], a[mf][3],
                          stageBase + aOffBase + mf * 16 * PITCH + k16 * 32);
#pragma unroll
                for (int np = 0; np < 4; np++) {
                    uint32_t b0, b1, b2, b3;
                    ldsm4(b0, b1, b2, b3,
                          stageBase + bOffBase + np * 16 * PITCH + k16 * 32);
#pragma unroll
                    for (int mf = 0; mf < 2; mf++) {
                        mma16816(acc[mf][np * 2],
                                 a[mf][0], a[mf][1], a[mf][2], a[mf][3], b0, b1);
                        mma16816(acc[mf][np * 2 + 1],
                                 a[mf][0], a[mf][1], a[mf][2], a[mf][3], b2, b3);
                    }
                }
            }
        }
        __syncthreads();

#pragma unroll
        for (int mf = 0; mf < 2; mf++) {
#pragma unroll
            for (int nf = 0; nf < 8; nf++) {
                int n = nt * 128 + wN + nf * 8 + (lane & 3) * 2;
                float2 cq = csq2[n >> 1];
                float v0 = cq.x - 2.f * acc[mf][nf][0];
                float v1 = cq.y - 2.f * acc[mf][nf][1];
                float v2 = cq.x - 2.f * acc[mf][nf][2];
                float v3 = cq.y - 2.f * acc[mf][nf][3];
                int s0 = mf * 2, s1 = mf * 2 + 1;
                ins4(cv1[s0], ci1[s0], cv2[s0], ci2[s0], cv3[s0], ci3[s0], cv4[s0], v0, n);
                ins4(cv1[s0], ci1[s0], cv2[s0], ci2[s0], cv3[s0], ci3[s0], cv4[s0], v1, n + 1);
                ins4(cv1[s1], ci1[s1], cv2[s1], ci2[s1], cv3[s1], ci3[s1], cv4[s1], v2, n);
                ins4(cv1[s1], ci1[s1], cv2[s1], ci2[s1], cv3[s1], ci3[s1], cv4[s1], v3, n + 1);
            }
        }
    }

#pragma unroll
    for (int s = 0; s < 4; s++) {
        int row = rowBase + wM + (s >> 1) * 16 + (s & 1) * 8 + (lane >> 2);
        int contrib = (wid >> 2) * 4 + (lane & 3);
        size_t base = ((size_t)row * 8 + contrib) * 2;
        g_cand[base] = make_uint4(__float_as_uint(cv1[s]), (uint32_t)ci1[s],
                                  __float_as_uint(cv2[s]), (uint32_t)ci2[s]);
        g_cand[base + 1] = make_uint4(__float_as_uint(cv3[s]), (uint32_t)ci3[s],
                                      __float_as_uint(cv4[s]), 0u);
    }
}

// ---------------------------------------------------------------------------
// window computation shared by rotate/fixup: returns fast, idx (if fast)
// ---------------------------------------------------------------------------
__device__ __forceinline__ void load_cand_window(
    int row, int qi, int lane,
    float& v1, int& i1, float& v2, int& i2, float& v3, int& i3, float& v4,
    float& m, float& win, float nz, float nl)
{
    v1 = INFINITY; v2 = INFINITY; v3 = INFINITY; v4 = INFINITY;
    i1 = 0x7fffffff; i2 = 0x7fffffff; i3 = 0x7fffffff;
    if (lane < 8) {
        uint4 a = g_cand[((size_t)row * 8 + lane) * 2];
        uint4 b = g_cand[((size_t)row * 8 + lane) * 2 + 1];
        v1 = __uint_as_float(a.x); i1 = (int)a.y;
        v2 = __uint_as_float(a.z); i2 = (int)a.w;
        v3 = __uint_as_float(b.x); i3 = (int)b.y;
        v4 = __uint_as_float(b.z);
    }
    m = v1;
#pragma unroll
    for (int o = 16; o; o >>= 1) m = fminf(m, __shfl_xor_sync(0xFFFFFFFFu, m, o));
    float ncmax = sqrtf(__int_as_float(g_cmaxi[qi]));
    float nlcmax = sqrtf(__int_as_float(g_nlcmaxi[qi]));
    win = m + 4.f * (nl * ncmax + (nz + nl) * nlcmax) + 0.2f;
}

// ---------------------------------------------------------------------------
// rotate: fast path only; defers slow rows to the queue. Warp per row.
// ---------------------------------------------------------------------------
__global__ void rotate_kernel(const float* __restrict__ cbs,
                              const float* __restrict__ x, int qi,
                              float* __restrict__ out_q,
                              float* __restrict__ out_if,
                              int writeIdx, int writeLoss, int writeConv)
{
    int row  = blockIdx.x * 4 + (threadIdx.x >> 5);
    int lane = threadIdx.x & 31;

    float zz = g_zz[row];
    float nz = sqrtf(zz);
    float nl = g_nl[row];

    float v1, v2, v3, v4, m, win;
    int i1, i2, i3;
    load_cand_window(row, qi, lane, v1, i1, v2, i2, v3, i3, v4, m, win, nz, nl);

    unsigned oflMask = __ballot_sync(0xFFFFFFFFu, v4 <= win);
    int myc = (v1 <= win ? 1 : 0) + (v2 <= win ? 1 : 0) + (v3 <= win ? 1 : 0);
    int tot = myc;
#pragma unroll
    for (int o = 16; o; o >>= 1) tot += __shfl_xor_sync(0xFFFFFFFFu, tot, o);

    if (oflMask != 0u || tot != 1) {
        if (lane == 0) g_queue[atomicAdd(&g_qcnt, 1)] = row;
        return;
    }
    unsigned bb = __ballot_sync(0xFFFFFFFFu, v1 == m);
    int idx = __shfl_sync(0xFFFFFFFFu, i1, __ffs(bb) - 1);

    do_rotation(cbs, x, qi, out_q, out_if, writeIdx, writeLoss, writeConv,
                row, lane, idx, zz, nz, nullptr, false);
}

// ---------------------------------------------------------------------------
// fixup: processes deferred rows from the queue; warp per row, work-stealing.
// ---------------------------------------------------------------------------
__global__ void fixup_kernel(const float* __restrict__ cbs,
                             const float* __restrict__ x, int qi,
                             float* __restrict__ out_q,
                             float* __restrict__ out_if,
                             int writeIdx, int writeLoss, int writeConv)
{
    __shared__ int candList[4][24];
    int wslot = threadIdx.x >> 5;
    int lane = threadIdx.x & 31;
    int qn = g_qcnt;
    const float* csq = g_cbsq + qi * CC;

    for (;;) {
        int t;
        if (lane == 0) t = atomicAdd(&g_qtake, 1);
        t = __shfl_sync(0xFFFFFFFFu, t, 0);
        if (t >= qn) return;
        int row = g_queue[t];

        float zz = g_zz[row];
        float nz = sqrtf(zz);
        float nl = g_nl[row];
        float v1, v2, v3, v4, m, win;
        int i1, i2, i3;
        load_cand_window(row, qi, lane, v1, i1, v2, i2, v3, i3, v4, m, win, nz, nl);

        unsigned oflMask = __ballot_sync(0xFFFFFFFFu, v4 <= win);
        int myc = (v1 <= win ? 1 : 0) + (v2 <= win ? 1 : 0) + (v3 <= win ? 1 : 0);
        int tot = myc;
#pragma unroll
        for (int o = 16; o; o >>= 1) tot += __shfl_xor_sync(0xFFFFFFFFu, tot, o);

        const float4* zp4 = (const float4*)(g_residual + (size_t)row * DD);
        float4 zv[4];
#pragma unroll
        for (int j = 0; j < 4; j++) zv[j] = zp4[lane + 32 * j];

        float bd = INFINITY; int bi = 0x7fffffff;
        if (tot <= 24) {
            int off = myc;
#pragma unroll
            for (int o = 1; o < 32; o <<= 1) {
                int tt = __shfl_up_sync(0xFFFFFFFFu, off, o);
                if (lane >= o) off += tt;
            }
            off -= myc;
            if (lane < 8) {
                int p = off;
                if (v1 <= win) candList[wslot][p++] = i1;
                if (v2 <= win) candList[wslot][p++] = i2;
                if (v3 <= win) candList[wslot][p++] = i3;
            }
            __syncwarp();
            // pipelined exact rescore (2-deep)
            for (int j = 0; j < tot; j += 2) {
                int c0 = candList[wslot][j];
                bool has1 = (j + 1 < tot);
                int c1 = has1 ? candList[wslot][j + 1] : c0;
                const float4* p0 = (const float4*)(cbs + ((size_t)qi * CC + c0) * DD);
                const float4* p1 = (const float4*)(cbs + ((size_t)qi * CC + c1) * DD);
                float s0 = 0.f, s1 = 0.f;
#pragma unroll
                for (int jj = 0; jj < 4; jj++) {
                    float4 q0 = p0[lane + 32 * jj];
                    float4 q1 = p1[lane + 32 * jj];
                    s0 += zv[jj].x*q0.x + zv[jj].y*q0.y + zv[jj].z*q0.z + zv[jj].w*q0.w;
                    s1 += zv[jj].x*q1.x + zv[jj].y*q1.y + zv[jj].z*q1.z + zv[jj].w*q1.w;
                }
#pragma unroll
                for (int o = 16; o; o >>= 1) {
                    s0 += __shfl_xor_sync(0xFFFFFFFFu, s0, o);
                    s1 += __shfl_xor_sync(0xFFFFFFFFu, s1, o);
                }
                float d0 = csq[c0] - 2.f * s0;
                if (d0 < bd || (d0 == bd && c0 < bi)) { bd = d0; bi = c0; }
                if (has1) {
                    float d1 = csq[c1] - 2.f * s1;
                    if (d1 < bd || (d1 == bd && c1 < bi)) { bd = d1; bi = c1; }
                }
            }
            // slot-local exact rescan for overflowed slots (pipelined 2-deep)
            unsigned om = oflMask;
            while (om) {
                int sl = __ffs(om) - 1; om &= om - 1;
                int wNs = (sl >> 2) * 64;
                int l2  = (sl & 3) * 2;
                for (int j = 0; j < 128; j += 2) {
                    int n0 = (j >> 4) * 128 + wNs + ((j >> 1) & 7) * 8 + l2 + (j & 1);
                    int jb = j + 1;
                    int n1 = (jb >> 4) * 128 + wNs + ((jb >> 1) & 7) * 8 + l2 + (jb & 1);
                    const float4* p0 = (const float4*)(cbs + ((size_t)qi * CC + n0) * DD);
                    const float4* p1 = (const float4*)(cbs + ((size_t)qi * CC + n1) * DD);
                    float s0 = 0.f, s1 = 0.f;
#pragma unroll
                    for (int jj = 0; jj < 4; jj++) {
                        float4 q0 = p0[lane + 32 * jj];
                        float4 q1 = p1[lane + 32 * jj];
                        s0 += zv[jj].x*q0.x + zv[jj].y*q0.y + zv[jj].z*q0.z + zv[jj].w*q0.w;
                        s1 += zv[jj].x*q1.x + zv[jj].y*q1.y + zv[jj].z*q1.z + zv[jj].w*q1.w;
                    }
#pragma unroll
                    for (int o = 16; o; o >>= 1) {
                        s0 += __shfl_xor_sync(0xFFFFFFFFu, s0, o);
                        s1 += __shfl_xor_sync(0xFFFFFFFFu, s1, o);
                    }
                    float d0 = csq[n0] - 2.f * s0;
                    float d1 = csq[n1] - 2.f * s1;
                    if (d0 < bd || (d0 == bd && n0 < bi)) { bd = d0; bi = n0; }
                    if (d1 < bd || (d1 == bd && n1 < bi)) { bd = d1; bi = n1; }
                }
            }
        } else {
            // extreme fallback: exact full scan
            for (int c = 0; c < CC; c++) {
                const float4* p0 = (const float4*)(cbs + ((size_t)qi * CC + c) * DD);
                float s0 = 0.f;
#pragma unroll
                for (int jj = 0; jj < 4; jj++) {
                    float4 q0 = p0[lane + 32 * jj];
                    s0 += zv[jj].x*q0.x + zv[jj].y*q0.y + zv[jj].z*q0.z + zv[jj].w*q0.w;
                }
#pragma unroll
                for (int o = 16; o; o >>= 1) s0 += __shfl_xor_sync(0xFFFFFFFFu, s0, o);
                float d0 = csq[c] - 2.f * s0;
                if (d0 < bd || (d0 == bd && c < bi)) { bd = d0; bi = c; }
            }
        }

        do_rotation(cbs, x, qi, out_q, out_if, writeIdx, writeLoss, writeConv,
                    row, lane, bi, zz, nz, zv, true);
    }
}

// ---------------------------------------------------------------------------
__global__ void final_kernel(float* __restrict__ out_loss) {
    int i = threadIdx.x;
    if (i < BQ) out_loss[i] = g_loss[i] / (float)((size_t)MROWS * DD);
}

// ---------------------------------------------------------------------------
extern "C" void kernel_launch(void* const* d_in, const int* in_sizes, int n_in,
                              void* d_out, int out_size) {
    const float* x   = (const float*)d_in[0];
    const float* cbs = (const float*)d_in[1];
    if (n_in >= 2 && in_sizes[0] == BQ * CC * DD && in_sizes[1] == MROWS * DD) {
        const float* t = x; x = cbs; cbs = t;
    }

    float* out = (float*)d_out;
    const long long qElems = (long long)MROWS * DD;
    const long long iElems = (long long)MROWS * BQ;
    float* out_q = out;
    float* out_i = out + qElems;
    float* out_l = out + qElems + iElems;
    int haveIdx  = (out_size >= qElems + iElems) ? 1 : 0;
    int haveLoss = (out_size >= qElems + iElems + BQ) ? 1 : 0;

    static int attrSet = 0;
    if (!attrSet) {
        cudaFuncSetAttribute(dist_mma_kernel,
                             cudaFuncAttributeMaxDynamicSharedMemorySize, SMEM_DYN);
        attrSet = 1;
    }

    init_kernel<<<MROWS / 8, 256>>>(x);
    cbsq_kernel<<<BQ * CC / 8, 256>>>(cbs);

    for (int qi = 0; qi < BQ; qi++) {
        dist_mma_kernel<<<MROWS / 128, 256, SMEM_DYN>>>(qi);
        rotate_kernel<<<MROWS / 4, 128>>>(cbs, x, qi, out_q, out_i,
                                          haveIdx, haveLoss, qi < BQ - 1);
        fixup_kernel<<<296, 128>>>(cbs, x, qi, out_q, out_i,
                                   haveIdx, haveLoss, qi < BQ - 1);
    }

    if (haveLoss) final_kernel<<<1, 32>>>(out_l);
}

// round 13
// speedup vs baseline: 1.2149x; 1.2149x over previous
#include <cuda_runtime.h>
#include <cuda_bf16.h>
#include <math.h>
#include <stdint.h>

#define BQ 8
#define CC 1024
#define DD 512
#define MROWS 32768            // B*N = 16*2048
#define EPSF 1e-6f

// ---- scratch (device globals; no allocation allowed) ----
__device__ float g_residual[(size_t)MROWS * DD];   // 64 MB fp32 residual
__device__ uint4 g_res_h4[(size_t)MROWS * 64];     // 32 MB bf16 hi  [row][512]
__device__ uint4 g_cb_h4[(size_t)BQ * CC * 64];    // 8 MB bf16 hi codebooks
__device__ float g_cbsq[BQ * CC];
__device__ float g_nl[MROWS];                      // per-row lo-norm
__device__ float g_zz[MROWS];                      // per-row ||r||^2
__device__ int   g_cmaxi[BQ];                      // max csq per codebook (bits)
__device__ int   g_nlcmaxi[BQ];                    // max lo-norm^2 per codebook
__device__ uint4 g_cand[(size_t)MROWS * 16];       // per row: 8 contribs x 2 uint4
__device__ float g_loss[BQ];

// ============================================================================
// portable PTX helpers
// ============================================================================
__device__ __forceinline__ uint32_t smem_to_u32(const void* p) {
    uint32_t a;
    asm("{ .reg .u64 t; cvta.to.shared.u64 t, %1; cvt.u32.u64 %0, t; }"
        : "=r"(a) : "l"(p));
    return a;
}
__device__ __forceinline__ void cpasync16(uint32_t dst, const void* src) {
    asm volatile("cp.async.cg.shared.global [%0], [%1], 16;" :: "r"(dst), "l"(src));
}
#define CP_COMMIT() asm volatile("cp.async.commit_group;" ::: "memory")
#define CP_WAIT(n)  asm volatile("cp.async.wait_group %0;" :: "n"(n) : "memory")

__device__ __forceinline__ void ldsm4(uint32_t& r0, uint32_t& r1, uint32_t& r2,
                                      uint32_t& r3, uint32_t addr) {
    asm volatile("ldmatrix.sync.aligned.m8n8.x4.shared.b16 {%0,%1,%2,%3}, [%4];"
                 : "=r"(r0), "=r"(r1), "=r"(r2), "=r"(r3) : "r"(addr));
}
__device__ __forceinline__ void mma16816(float* c, uint32_t a0, uint32_t a1,
                                         uint32_t a2, uint32_t a3,
                                         uint32_t b0, uint32_t b1) {
    asm volatile(
        "mma.sync.aligned.m16n8k16.row.col.f32.bf16.bf16.f32 "
        "{%0,%1,%2,%3}, {%4,%5,%6,%7}, {%8,%9}, {%0,%1,%2,%3};"
        : "+f"(c[0]), "+f"(c[1]), "+f"(c[2]), "+f"(c[3])
        : "r"(a0), "r"(a1), "r"(a2), "r"(a3), "r"(b0), "r"(b1));
}

__device__ __forceinline__ ushort4 hi4(float4 v) {
    ushort4 h;
    h.x = __bfloat16_as_ushort(__float2bfloat16_rn(v.x));
    h.y = __bfloat16_as_ushort(__float2bfloat16_rn(v.y));
    h.z = __bfloat16_as_ushort(__float2bfloat16_rn(v.z));
    h.w = __bfloat16_as_ushort(__float2bfloat16_rn(v.w));
    return h;
}
__device__ __forceinline__ float losq4(float4 v, ushort4 h) {
    float dx = v.x - __bfloat162float(__ushort_as_bfloat16(h.x));
    float dy = v.y - __bfloat162float(__ushort_as_bfloat16(h.y));
    float dz = v.z - __bfloat162float(__ushort_as_bfloat16(h.z));
    float dw = v.w - __bfloat162float(__ushort_as_bfloat16(h.w));
    return dx*dx + dy*dy + dz*dz + dw*dw;
}

// top-3 + 4th-value sentinel insert (cheap chain — keeps dist at the MMA floor)
__device__ __forceinline__ void ins4(float& v1, int& i1, float& v2, int& i2,
                                     float& v3, int& i3, float& v4,
                                     float v, int n) {
    if (v < v4) {
        if (v < v1)      { v4 = v3; v3 = v2; i3 = i2; v2 = v1; i2 = i1; v1 = v; i1 = n; }
        else if (v < v2) { v4 = v3; v3 = v2; i3 = i2; v2 = v; i2 = n; }
        else if (v < v3) { v4 = v3; v3 = v; i3 = n; }
        else             { v4 = v; }
    }
}

// warp-cooperative exact distance of row (zv in regs) vs code c
__device__ __forceinline__ float exact_d(const float* __restrict__ cbs,
                                         const float* __restrict__ csq,
                                         int qi, int c, const float4* zv, int lane) {
    const float4* qp4 = (const float4*)(cbs + ((size_t)qi * CC + c) * DD);
    float s = 0.f;
#pragma unroll
    for (int jj = 0; jj < 4; jj++) {
        float4 q = qp4[lane + 32 * jj];
        s += zv[jj].x*q.x + zv[jj].y*q.y + zv[jj].z*q.z + zv[jj].w*q.w;
    }
#pragma unroll
    for (int o = 16; o; o >>= 1) s += __shfl_xor_sync(0xFFFFFFFFu, s, o);
    return csq[c] - 2.f * s;
}

// ---------------------------------------------------------------------------
// init: residual = x (fp32 + bf16 hi), zz + nl per row, reset loss/cmax.
// ---------------------------------------------------------------------------
__global__ void init_kernel(const float* __restrict__ x) {
    int row  = blockIdx.x * 8 + (threadIdx.x >> 5);
    int lane = threadIdx.x & 31;
    const float4* xp = (const float4*)(x + (size_t)row * DD);
    float4* rp = (float4*)(g_residual + (size_t)row * DD);
    ushort4* rh = (ushort4*)g_res_h4;
    float nls = 0.f, zz = 0.f;
#pragma unroll
    for (int j = 0; j < 4; j++) {
        float4 v = xp[lane + 32 * j];
        rp[lane + 32 * j] = v;
        ushort4 h = hi4(v);
        rh[(size_t)row * 128 + lane + 32 * j] = h;
        nls += losq4(v, h);
        zz += v.x*v.x + v.y*v.y + v.z*v.z + v.w*v.w;
    }
#pragma unroll
    for (int o = 16; o; o >>= 1) {
        nls += __shfl_xor_sync(0xFFFFFFFFu, nls, o);
        zz  += __shfl_xor_sync(0xFFFFFFFFu, zz, o);
    }
    if (lane == 0) { g_nl[row] = sqrtf(nls); g_zz[row] = zz; }
    if (blockIdx.x == 0 && threadIdx.x < BQ) {
        g_loss[threadIdx.x] = 0.f;
        g_cmaxi[threadIdx.x] = 0;
        g_nlcmaxi[threadIdx.x] = 0;
    }
}

// ---------------------------------------------------------------------------
// codebook: cb_sq + bf16 hi + per-codebook max csq and max lo-norm^2
// ---------------------------------------------------------------------------
__global__ void cbsq_kernel(const float* __restrict__ cb) {
    int row  = blockIdx.x * 8 + (threadIdx.x >> 5);
    int lane = threadIdx.x & 31;
    const float4* p = (const float4*)(cb + (size_t)row * DD);
    ushort4* ch = (ushort4*)g_cb_h4;
    float s = 0.f, lsq = 0.f;
#pragma unroll
    for (int j = 0; j < 4; j++) {
        float4 v = p[lane + 32 * j];
        s += v.x * v.x + v.y * v.y + v.z * v.z + v.w * v.w;
        ushort4 h = hi4(v);
        ch[(size_t)row * 128 + lane + 32 * j] = h;
        lsq += losq4(v, h);
    }
#pragma unroll
    for (int o = 16; o; o >>= 1) {
        s += __shfl_xor_sync(0xFFFFFFFFu, s, o);
        lsq += __shfl_xor_sync(0xFFFFFFFFu, lsq, o);
    }
    if (lane == 0) {
        g_cbsq[row] = s;
        atomicMax(&g_cmaxi[row >> 10], __float_as_int(s));
        atomicMax(&g_nlcmaxi[row >> 10], __float_as_int(lsq));
    }
}

// ---------------------------------------------------------------------------
// hh-only distance GEMM (K=512 bf16), per-thread top-3 + v4 candidate lists.
// (floor-proven R8/R11 configuration, untouched)
// ---------------------------------------------------------------------------
#define PITCH   80
#define TILEB   (128 * PITCH)
#define STAGEB  (2 * TILEB)
#define NKC     16
#define SMEM_DYN (4 * STAGEB)

__device__ __forceinline__ void issue_chunk(
    uint32_t sb, int rowBase, int qi, int nt, int kc, int stage)
{
    int koff = kc * 64;
    uint32_t base = sb + stage * STAGEB;
    int tid = threadIdx.x;
    size_t bRow = (size_t)(qi * CC + nt * 128);
#pragma unroll
    for (int i = 0; i < 2; i++) {
        int g = tid + 256 * i;
        int r = g >> 2, c = g & 3;
        cpasync16(base + r * PITCH + c * 16,
                  (const char*)g_res_h4 + (size_t)(rowBase + r) * 1024 + koff + c * 16);
        cpasync16(base + TILEB + r * PITCH + c * 16,
                  (const char*)g_cb_h4 + (bRow + r) * 1024 + koff + c * 16);
    }
}

__global__ __launch_bounds__(256, 2) void dist_mma_kernel(int qi)
{
    extern __shared__ char smem[];
    uint32_t sb = smem_to_u32(smem);

    const int tid  = threadIdx.x;
    const int wid  = tid >> 5;
    const int lane = tid & 31;
    const int rowBase = blockIdx.x * 128;
    const int wM = (wid & 3) * 32;
    const int wN = (wid >> 2) * 64;

    const int aRow = lane & 15;
    const int aCol = (lane >> 4) * 16;
    const int bRowL = (lane & 7) + ((lane >> 4) << 3);
    const int bColL = ((lane >> 3) & 1) * 16;
    const uint32_t aOffBase = (uint32_t)((wM + aRow) * PITCH + aCol);
    const uint32_t bOffBase = (uint32_t)(TILEB + (wN + bRowL) * PITCH + bColL);

    const float2* csq2 = (const float2*)(g_cbsq + qi * CC);

    float cv1[4], cv2[4], cv3[4], cv4[4];
    int   ci1[4], ci2[4], ci3[4];
#pragma unroll
    for (int s = 0; s < 4; s++) {
        cv1[s] = INFINITY; cv2[s] = INFINITY; cv3[s] = INFINITY; cv4[s] = INFINITY;
        ci1[s] = 0x7fffffff; ci2[s] = 0x7fffffff; ci3[s] = 0x7fffffff;
    }

#pragma unroll 1
    for (int nt = 0; nt < 8; nt++) {
        float acc[2][8][4];
#pragma unroll
        for (int mf = 0; mf < 2; mf++)
#pragma unroll
            for (int nf = 0; nf < 8; nf++)
#pragma unroll
                for (int e = 0; e < 4; e++) acc[mf][nf][e] = 0.f;

        issue_chunk(sb, rowBase, qi, nt, 0, 0); CP_COMMIT();
        issue_chunk(sb, rowBase, qi, nt, 1, 1); CP_COMMIT();
        issue_chunk(sb, rowBase, qi, nt, 2, 2); CP_COMMIT();

#pragma unroll 1
        for (int kc = 0; kc < NKC; kc++) {
            if (kc < NKC - 2) { CP_WAIT(2); } else if (kc == NKC - 2) { CP_WAIT(1); }
            else { CP_WAIT(0); }
            __syncthreads();
            if (kc + 3 < NKC) {
                issue_chunk(sb, rowBase, qi, nt, kc + 3, (kc + 3) & 3);
                CP_COMMIT();
            }

            uint32_t stageBase = sb + (kc & 3) * STAGEB;
#pragma unroll
            for (int k16 = 0; k16 < 2; k16++) {
                uint32_t a[2][4];
#pragma unroll
                for (int mf = 0; mf < 2; mf++)
                    ldsm4(a[mf][0], a[mf][1], a[mf][2], a[mf][3],
                          stageBase + aOffBase + mf * 16 * PITCH + k16 * 32);
#pragma unroll
                for (int np = 0; np < 4; np++) {
                    uint32_t b0, b1, b2, b3;
                    ldsm4(b0, b1, b2, b3,
                          stageBase + bOffBase + np * 16 * PITCH + k16 * 32);
#pragma unroll
                    for (int mf = 0; mf < 2; mf++) {
                        mma16816(acc[mf][np * 2],
                                 a[mf][0], a[mf][1], a[mf][2], a[mf][3], b0, b1);
                        mma16816(acc[mf][np * 2 + 1],
                                 a[mf][0], a[mf][1], a[mf][2], a[mf][3], b2, b3);
                    }
                }
            }
        }
        __syncthreads();

#pragma unroll
        for (int mf = 0; mf < 2; mf++) {
#pragma unroll
            for (int nf = 0; nf < 8; nf++) {
                int n = nt * 128 + wN + nf * 8 + (lane & 3) * 2;
                float2 cq = csq2[n >> 1];
                float v0 = cq.x - 2.f * acc[mf][nf][0];
                float v1 = cq.y - 2.f * acc[mf][nf][1];
                float v2 = cq.x - 2.f * acc[mf][nf][2];
                float v3 = cq.y - 2.f * acc[mf][nf][3];
                int s0 = mf * 2, s1 = mf * 2 + 1;
                ins4(cv1[s0], ci1[s0], cv2[s0], ci2[s0], cv3[s0], ci3[s0], cv4[s0], v0, n);
                ins4(cv1[s0], ci1[s0], cv2[s0], ci2[s0], cv3[s0], ci3[s0], cv4[s0], v1, n + 1);
                ins4(cv1[s1], ci1[s1], cv2[s1], ci2[s1], cv3[s1], ci3[s1], cv4[s1], v2, n);
                ins4(cv1[s1], ci1[s1], cv2[s1], ci2[s1], cv3[s1], ci3[s1], cv4[s1], v3, n + 1);
            }
        }
    }

#pragma unroll
    for (int s = 0; s < 4; s++) {
        int row = rowBase + wM + (s >> 1) * 16 + (s & 1) * 8 + (lane >> 2);
        int contrib = (wid >> 2) * 4 + (lane & 3);
        size_t base = ((size_t)row * 8 + contrib) * 2;
        g_cand[base] = make_uint4(__float_as_uint(cv1[s]), (uint32_t)ci1[s],
                                  __float_as_uint(cv2[s]), (uint32_t)ci2[s]);
        g_cand[base + 1] = make_uint4(__float_as_uint(cv3[s]), (uint32_t)ci3[s],
                                      __float_as_uint(cv4[s]), 0u);
    }
}

// ---------------------------------------------------------------------------
// Exact argmin selection with exact-first thresholding + rotation.
// Warp per row, 4 rows / 128-thread block. No block-level sync.
// ---------------------------------------------------------------------------
__global__ void rotate_kernel(const float* __restrict__ cbs,
                              const float* __restrict__ x, int qi,
                              float* __restrict__ out_q,
                              float* __restrict__ out_if,
                              int writeIdx, int writeLoss, int writeConv)
{
    __shared__ float candV[4][24];
    __shared__ int   candI[4][24];
    __shared__ int   candC[4][24];
    int wslot = threadIdx.x >> 5;
    int row  = blockIdx.x * 4 + (threadIdx.x >> 5);
    int lane = threadIdx.x & 31;
    float* zp = g_residual + (size_t)row * DD;
    const float4* zp4 = (const float4*)zp;

    float zz = g_zz[row];
    float nz = sqrtf(zz);
    float nl = g_nl[row];
    float ncmax = sqrtf(__int_as_float(g_cmaxi[qi]));
    float nlcmax = sqrtf(__int_as_float(g_nlcmaxi[qi]));
    const float* csq = g_cbsq + qi * CC;

    float v1 = INFINITY, v2 = INFINITY, v3 = INFINITY, v4 = INFINITY;
    int i1 = 0x7fffffff, i2 = 0x7fffffff, i3 = 0x7fffffff;
    if (lane < 8) {
        uint4 a = g_cand[((size_t)row * 8 + lane) * 2];
        uint4 b = g_cand[((size_t)row * 8 + lane) * 2 + 1];
        v1 = __uint_as_float(a.x); i1 = (int)a.y;
        v2 = __uint_as_float(a.z); i2 = (int)a.w;
        v3 = __uint_as_float(b.x); i3 = (int)b.y;
        v4 = __uint_as_float(b.z);
    }
    float m = v1;
#pragma unroll
    for (int o = 16; o; o >>= 1) m = fminf(m, __shfl_xor_sync(0xFFFFFFFFu, m, o));
    float w1  = 2.f * (nl * ncmax + (nz + nl) * nlcmax) + 0.1f;  // one-sided bound
    float win = m + 2.f * w1;                                     // two-sided window

    unsigned oflMask = __ballot_sync(0xFFFFFFFFu, v4 <= win);
    int myc = (v1 <= win ? 1 : 0) + (v2 <= win ? 1 : 0) + (v3 <= win ? 1 : 0);
    int tot = myc;
#pragma unroll
    for (int o = 16; o; o >>= 1) tot += __shfl_xor_sync(0xFFFFFFFFu, tot, o);

    bool fast = (oflMask == 0u && tot == 1);
    float4 zv[4];
    int idx;
    if (fast) {
        unsigned bb = __ballot_sync(0xFFFFFFFFu, v1 == m);
        idx = __shfl_sync(0xFFFFFFFFu, i1, __ffs(bb) - 1);
    } else {
        // need z data for exact rescoring
#pragma unroll
        for (int j = 0; j < 4; j++) zv[j] = zp4[lane + 32 * j];

        if (tot <= 24) {
            // gather listed in-window candidates (value + index)
            int off = myc;
#pragma unroll
            for (int o = 1; o < 32; o <<= 1) {
                int t = __shfl_up_sync(0xFFFFFFFFu, off, o);
                if (lane >= o) off += t;
            }
            off -= myc;
            if (lane < 8) {
                int p = off;
                if (v1 <= win) { candV[wslot][p] = v1; candI[wslot][p] = i1; p++; }
                if (v2 <= win) { candV[wslot][p] = v2; candI[wslot][p] = i2; p++; }
                if (v3 <= win) { candV[wslot][p] = v3; candI[wslot][p] = i3; p++; }
            }
            __syncwarp();

            // exact-first: rescore the d~-argmin, derive one-sided threshold
            unsigned bb = __ballot_sync(0xFFFFFFFFu, v1 == m);
            int cstar = __shfl_sync(0xFFFFFFFFu, i1, __ffs(bb) - 1);
            float bd = exact_d(cbs, csq, qi, cstar, zv, lane);
            int bi = cstar;
            float thr = bd + w1;

            // compact survivors (v <= thr, exclude cstar)
            int keep = 0, cidx = 0;
            if (lane < tot) {
                float cvv = candV[wslot][lane];
                cidx = candI[wslot][lane];
                keep = (cvv <= thr && cidx != cstar) ? 1 : 0;
            }
            unsigned km = __ballot_sync(0xFFFFFFFFu, keep);
            if (keep) candC[wslot][__popc(km & ((1u << lane) - 1))] = cidx;
            int tot2 = __popc(km);
            __syncwarp();

            // pipelined exact rescore of survivors (2-deep)
            for (int j = 0; j < tot2; j += 2) {
                int c0 = candC[wslot][j];
                bool has1 = (j + 1 < tot2);
                int c1 = has1 ? candC[wslot][j + 1] : c0;
                const float4* p0 = (const float4*)(cbs + ((size_t)qi * CC + c0) * DD);
                const float4* p1 = (const float4*)(cbs + ((size_t)qi * CC + c1) * DD);
                float s0 = 0.f, s1 = 0.f;
#pragma unroll
                for (int jj = 0; jj < 4; jj++) {
                    float4 q0 = p0[lane + 32 * jj];
                    float4 q1 = p1[lane + 32 * jj];
                    s0 += zv[jj].x*q0.x + zv[jj].y*q0.y + zv[jj].z*q0.z + zv[jj].w*q0.w;
                    s1 += zv[jj].x*q1.x + zv[jj].y*q1.y + zv[jj].z*q1.z + zv[jj].w*q1.w;
                }
#pragma unroll
                for (int o = 16; o; o >>= 1) {
                    s0 += __shfl_xor_sync(0xFFFFFFFFu, s0, o);
                    s1 += __shfl_xor_sync(0xFFFFFFFFu, s1, o);
                }
                float d0 = csq[c0] - 2.f * s0;
                if (d0 < bd || (d0 == bd && c0 < bi)) { bd = d0; bi = c0; }
                if (has1) {
                    float d1 = csq[c1] - 2.f * s1;
                    if (d1 < bd || (d1 == bd && c1 < bi)) { bd = d1; bi = c1; }
                }
            }

            // slot rescans gated on the HALVED threshold (v4 <= bd + w1)
            unsigned om = __ballot_sync(0xFFFFFFFFu, v4 <= bd + w1);
            while (om) {
                int sl = __ffs(om) - 1; om &= om - 1;
                int wNs = (sl >> 2) * 64;
                int l2  = (sl & 3) * 2;
                for (int j = 0; j < 128; j += 2) {
                    int n0 = (j >> 4) * 128 + wNs + ((j >> 1) & 7) * 8 + l2 + (j & 1);
                    int jb = j + 1;
                    int n1 = (jb >> 4) * 128 + wNs + ((jb >> 1) & 7) * 8 + l2 + (jb & 1);
                    const float4* p0 = (const float4*)(cbs + ((size_t)qi * CC + n0) * DD);
                    const float4* p1 = (const float4*)(cbs + ((size_t)qi * CC + n1) * DD);
                    float s0 = 0.f, s1 = 0.f;
#pragma unroll
                    for (int jj = 0; jj < 4; jj++) {
                        float4 q0 = p0[lane + 32 * jj];
                        float4 q1 = p1[lane + 32 * jj];
                        s0 += zv[jj].x*q0.x + zv[jj].y*q0.y + zv[jj].z*q0.z + zv[jj].w*q0.w;
                        s1 += zv[jj].x*q1.x + zv[jj].y*q1.y + zv[jj].z*q1.z + zv[jj].w*q1.w;
                    }
#pragma unroll
                    for (int o = 16; o; o >>= 1) {
                        s0 += __shfl_xor_sync(0xFFFFFFFFu, s0, o);
                        s1 += __shfl_xor_sync(0xFFFFFFFFu, s1, o);
                    }
                    float d0 = csq[n0] - 2.f * s0;
                    float d1 = csq[n1] - 2.f * s1;
                    if (d0 < bd || (d0 == bd && n0 < bi)) { bd = d0; bi = n0; }
                    if (d1 < bd || (d1 == bd && n1 < bi)) { bd = d1; bi = n1; }
                }
            }
            idx = bi;
        } else {
            // extreme fallback: exact full scan
            float bd = INFINITY; int bi = 0x7fffffff;
            for (int c = 0; c < CC; c++) {
                float d = exact_d(cbs, csq, qi, c, zv, lane);
                if (d < bd || (d == bd && c < bi)) { bd = d; bi = c; }
            }
            idx = bi;
        }
    }

    // ---- load q (and z in fast path, overlapped), single zq reduction ----
    const float4* qp4 = (const float4*)(cbs + ((size_t)qi * CC + idx) * DD);
    float4 qv[4];
    if (fast) {
#pragma unroll
        for (int j = 0; j < 4; j++) { zv[j] = zp4[lane + 32 * j]; qv[j] = qp4[lane + 32 * j]; }
    } else {
#pragma unroll
        for (int j = 0; j < 4; j++) qv[j] = qp4[lane + 32 * j];
    }
    float zq = 0.f;
#pragma unroll
    for (int j = 0; j < 4; j++)
        zq += zv[j].x*qv[j].x + zv[j].y*qv[j].y + zv[j].z*qv[j].z + zv[j].w*qv[j].w;
#pragma unroll
    for (int o = 16; o; o >>= 1) zq += __shfl_xor_sync(0xFFFFFFFFu, zq, o);

    float qq = csq[idx];
    float ll = zz - 2.f * zq + qq;

    float nq = sqrtf(qq);
    float iz = 1.f / (nz + EPSF), iq = 1.f / (nq + EPSF);
    float s2 = zz * iz * iz + 2.f * zq * iz * iq + qq * iq * iq;
    float A2 = 2.f * (zz * iz + zq * iq) / s2;
    float Bc = 2.f * zz * iz * iq;
    float cz = 1.f - A2 * iz;
    float cq = Bc - A2 * iq;
    float sc = nq * iz;

    if (writeConv) {
        ushort4* rh = (ushort4*)g_res_h4;
        float nls = 0.f, zz2 = 0.f;
#pragma unroll
        for (int j = 0; j < 4; j++) {
            float4 z = zv[j], q = qv[j], t, r;
            t.x = (z.x * cz + q.x * cq) * sc;
            t.y = (z.y * cz + q.y * cq) * sc;
            t.z = (z.z * cz + q.z * cq) * sc;
            t.w = (z.w * cz + q.w * cq) * sc;
            r.x = z.x - t.x; r.y = z.y - t.y; r.z = z.z - t.z; r.w = z.w - t.w;
            ((float4*)zp)[lane + 32 * j] = r;
            ushort4 h = hi4(r);
            rh[(size_t)row * 128 + lane + 32 * j] = h;
            nls += losq4(r, h);
            zz2 += r.x*r.x + r.y*r.y + r.z*r.z + r.w*r.w;
        }
#pragma unroll
        for (int o = 16; o; o >>= 1) {
            nls += __shfl_xor_sync(0xFFFFFFFFu, nls, o);
            zz2 += __shfl_xor_sync(0xFFFFFFFFu, zz2, o);
        }
        if (lane == 0) { g_nl[row] = sqrtf(nls); g_zz[row] = zz2; }
    } else {
        const float4* xp4 = (const float4*)(x + (size_t)row * DD);
        float4* op4 = (float4*)(out_q + (size_t)row * DD);
#pragma unroll
        for (int j = 0; j < 4; j++) {
            float4 z = zv[j], q = qv[j], t, r, xv;
            t.x = (z.x * cz + q.x * cq) * sc;
            t.y = (z.y * cz + q.y * cq) * sc;
            t.z = (z.z * cz + q.z * cq) * sc;
            t.w = (z.w * cz + q.w * cq) * sc;
            r.x = z.x - t.x; r.y = z.y - t.y; r.z = z.z - t.z; r.w = z.w - t.w;
            xv = xp4[lane + 32 * j];
            op4[lane + 32 * j] = make_float4(xv.x - r.x, xv.y - r.y,
                                             xv.z - r.z, xv.w - r.w);
        }
    }

    if (writeIdx && lane == 0)
        out_if[(size_t)row * BQ + qi] = (float)idx;
    if (writeLoss && lane == 0)
        atomicAdd(&g_loss[qi], ll);
}

// ---------------------------------------------------------------------------
__global__ void final_kernel(float* __restrict__ out_loss) {
    int i = threadIdx.x;
    if (i < BQ) out_loss[i] = g_loss[i] / (float)((size_t)MROWS * DD);
}

// ---------------------------------------------------------------------------
extern "C" void kernel_launch(void* const* d_in, const int* in_sizes, int n_in,
                              void* d_out, int out_size) {
    const float* x   = (const float*)d_in[0];
    const float* cbs = (const float*)d_in[1];
    if (n_in >= 2 && in_sizes[0] == BQ * CC * DD && in_sizes[1] == MROWS * DD) {
        const float* t = x; x = cbs; cbs = t;
    }

    float* out = (float*)d_out;
    const long long qElems = (long long)MROWS * DD;
    const long long iElems = (long long)MROWS * BQ;
    float* out_q = out;
    float* out_i = out + qElems;
    float* out_l = out + qElems + iElems;
    int haveIdx  = (out_size >= qElems + iElems) ? 1 : 0;
    int haveLoss = (out_size >= qElems + iElems + BQ) ? 1 : 0;

    static int attrSet = 0;
    if (!attrSet) {
        cudaFuncSetAttribute(dist_mma_kernel,
                             cudaFuncAttributeMaxDynamicSharedMemorySize, SMEM_DYN);
        attrSet = 1;
    }

    init_kernel<<<MROWS / 8, 256>>>(x);
    cbsq_kernel<<<BQ * CC / 8, 256>>>(cbs);

    for (int qi = 0; qi < BQ; qi++) {
        dist_mma_kernel<<<MROWS / 128, 256, SMEM_DYN>>>(qi);
        rotate_kernel<<<MROWS / 4, 128>>>(cbs, x, qi, out_q, out_i,
                                          haveIdx, haveLoss, qi < BQ - 1);
    }

    if (haveLoss) final_kernel<<<1, 32>>>(out_l);
}

// round 14
// speedup vs baseline: 1.3153x; 1.0826x over previous
#include <cuda_runtime.h>
#include <cuda_fp16.h>
#include <math.h>
#include <stdint.h>

#define BQ 8
#define CC 1024
#define DD 512
#define MROWS 32768            // B*N = 16*2048
#define EPSF 1e-6f

// ---- scratch (device globals; no allocation allowed) ----
__device__ float g_residual[(size_t)MROWS * DD];   // 64 MB fp32 residual
__device__ uint4 g_res_h4[(size_t)MROWS * 64];     // 32 MB fp16 hi  [row][512]
__device__ uint4 g_cb_h4[(size_t)BQ * CC * 64];    // 8 MB fp16 hi codebooks
__device__ float g_cbsq[BQ * CC];
__device__ float g_nl[MROWS];                      // per-row lo-norm ||r - fp16(r)||
__device__ float g_zz[MROWS];                      // per-row ||r||^2
__device__ int   g_cmaxi[BQ];                      // max csq per codebook (bits)
__device__ int   g_nlcmaxi[BQ];                    // max lo-norm^2 per codebook
__device__ uint4 g_cand[(size_t)MROWS * 16];       // per row: 8 contribs x 2 uint4
__device__ float g_loss[BQ];

// ============================================================================
// portable PTX helpers
// ============================================================================
__device__ __forceinline__ uint32_t smem_to_u32(const void* p) {
    uint32_t a;
    asm("{ .reg .u64 t; cvta.to.shared.u64 t, %1; cvt.u32.u64 %0, t; }"
        : "=r"(a) : "l"(p));
    return a;
}
__device__ __forceinline__ void cpasync16(uint32_t dst, const void* src) {
    asm volatile("cp.async.cg.shared.global [%0], [%1], 16;" :: "r"(dst), "l"(src));
}
#define CP_COMMIT() asm volatile("cp.async.commit_group;" ::: "memory")
#define CP_WAIT(n)  asm volatile("cp.async.wait_group %0;" :: "n"(n) : "memory")

__device__ __forceinline__ void ldsm4(uint32_t& r0, uint32_t& r1, uint32_t& r2,
                                      uint32_t& r3, uint32_t addr) {
    asm volatile("ldmatrix.sync.aligned.m8n8.x4.shared.b16 {%0,%1,%2,%3}, [%4];"
                 : "=r"(r0), "=r"(r1), "=r"(r2), "=r"(r3) : "r"(addr));
}
// fp16 MMA, fp32 accumulate (same rate as bf16 on sm_103a legacy HMMA path)
__device__ __forceinline__ void mma16816(float* c, uint32_t a0, uint32_t a1,
                                         uint32_t a2, uint32_t a3,
                                         uint32_t b0, uint32_t b1) {
    asm volatile(
        "mma.sync.aligned.m16n8k16.row.col.f32.f16.f16.f32 "
        "{%0,%1,%2,%3}, {%4,%5,%6,%7}, {%8,%9}, {%0,%1,%2,%3};"
        : "+f"(c[0]), "+f"(c[1]), "+f"(c[2]), "+f"(c[3])
        : "r"(a0), "r"(a1), "r"(a2), "r"(a3), "r"(b0), "r"(b1));
}

// fp16 hi conversion (4 elements)
__device__ __forceinline__ ushort4 hi4(float4 v) {
    ushort4 h;
    h.x = __half_as_ushort(__float2half_rn(v.x));
    h.y = __half_as_ushort(__float2half_rn(v.y));
    h.z = __half_as_ushort(__float2half_rn(v.z));
    h.w = __half_as_ushort(__float2half_rn(v.w));
    return h;
}
__device__ __forceinline__ float losq4(float4 v, ushort4 h) {
    float dx = v.x - __half2float(__ushort_as_half(h.x));
    float dy = v.y - __half2float(__ushort_as_half(h.y));
    float dz = v.z - __half2float(__ushort_as_half(h.z));
    float dw = v.w - __half2float(__ushort_as_half(h.w));
    return dx*dx + dy*dy + dz*dz + dw*dw;
}

// top-3 + 4th-value sentinel insert (cheap chain — keeps dist at the MMA floor)
__device__ __forceinline__ void ins4(float& v1, int& i1, float& v2, int& i2,
                                     float& v3, int& i3, float& v4,
                                     float v, int n) {
    if (v < v4) {
        if (v < v1)      { v4 = v3; v3 = v2; i3 = i2; v2 = v1; i2 = i1; v1 = v; i1 = n; }
        else if (v < v2) { v4 = v3; v3 = v2; i3 = i2; v2 = v; i2 = n; }
        else if (v < v3) { v4 = v3; v3 = v; i3 = n; }
        else             { v4 = v; }
    }
}

// warp-cooperative exact distance of row (zv in regs) vs code c
__device__ __forceinline__ float exact_d(const float* __restrict__ cbs,
                                         const float* __restrict__ csq,
                                         int qi, int c, const float4* zv, int lane) {
    const float4* qp4 = (const float4*)(cbs + ((size_t)qi * CC + c) * DD);
    float s = 0.f;
#pragma unroll
    for (int jj = 0; jj < 4; jj++) {
        float4 q = qp4[lane + 32 * jj];
        s += zv[jj].x*q.x + zv[jj].y*q.y + zv[jj].z*q.z + zv[jj].w*q.w;
    }
#pragma unroll
    for (int o = 16; o; o >>= 1) s += __shfl_xor_sync(0xFFFFFFFFu, s, o);
    return csq[c] - 2.f * s;
}

// ---------------------------------------------------------------------------
// init: residual = x (fp32 + fp16 hi), zz + nl per row, reset loss/cmax.
// ---------------------------------------------------------------------------
__global__ void init_kernel(const float* __restrict__ x) {
    int row  = blockIdx.x * 8 + (threadIdx.x >> 5);
    int lane = threadIdx.x & 31;
    const float4* xp = (const float4*)(x + (size_t)row * DD);
    float4* rp = (float4*)(g_residual + (size_t)row * DD);
    ushort4* rh = (ushort4*)g_res_h4;
    float nls = 0.f, zz = 0.f;
#pragma unroll
    for (int j = 0; j < 4; j++) {
        float4 v = xp[lane + 32 * j];
        rp[lane + 32 * j] = v;
        ushort4 h = hi4(v);
        rh[(size_t)row * 128 + lane + 32 * j] = h;
        nls += losq4(v, h);
        zz += v.x*v.x + v.y*v.y + v.z*v.z + v.w*v.w;
    }
#pragma unroll
    for (int o = 16; o; o >>= 1) {
        nls += __shfl_xor_sync(0xFFFFFFFFu, nls, o);
        zz  += __shfl_xor_sync(0xFFFFFFFFu, zz, o);
    }
    if (lane == 0) { g_nl[row] = sqrtf(nls); g_zz[row] = zz; }
    if (blockIdx.x == 0 && threadIdx.x < BQ) {
        g_loss[threadIdx.x] = 0.f;
        g_cmaxi[threadIdx.x] = 0;
        g_nlcmaxi[threadIdx.x] = 0;
    }
}

// ---------------------------------------------------------------------------
// codebook: cb_sq + fp16 hi + per-codebook max csq and max lo-norm^2
// ---------------------------------------------------------------------------
__global__ void cbsq_kernel(const float* __restrict__ cb) {
    int row  = blockIdx.x * 8 + (threadIdx.x >> 5);
    int lane = threadIdx.x & 31;
    const float4* p = (const float4*)(cb + (size_t)row * DD);
    ushort4* ch = (ushort4*)g_cb_h4;
    float s = 0.f, lsq = 0.f;
#pragma unroll
    for (int j = 0; j < 4; j++) {
        float4 v = p[lane + 32 * j];
        s += v.x * v.x + v.y * v.y + v.z * v.z + v.w * v.w;
        ushort4 h = hi4(v);
        ch[(size_t)row * 128 + lane + 32 * j] = h;
        lsq += losq4(v, h);
    }
#pragma unroll
    for (int o = 16; o; o >>= 1) {
        s += __shfl_xor_sync(0xFFFFFFFFu, s, o);
        lsq += __shfl_xor_sync(0xFFFFFFFFu, lsq, o);
    }
    if (lane == 0) {
        g_cbsq[row] = s;
        atomicMax(&g_cmaxi[row >> 10], __float_as_int(s));
        atomicMax(&g_nlcmaxi[row >> 10], __float_as_int(lsq));
    }
}

// ---------------------------------------------------------------------------
// hi-only distance GEMM (K=512 fp16), per-thread top-3 + v4 candidate lists.
// (floor-proven configuration, only the operand type changed)
// ---------------------------------------------------------------------------
#define PITCH   80
#define TILEB   (128 * PITCH)
#define STAGEB  (2 * TILEB)
#define NKC     16
#define SMEM_DYN (4 * STAGEB)

__device__ __forceinline__ void issue_chunk(
    uint32_t sb, int rowBase, int qi, int nt, int kc, int stage)
{
    int koff = kc * 64;
    uint32_t base = sb + stage * STAGEB;
    int tid = threadIdx.x;
    size_t bRow = (size_t)(qi * CC + nt * 128);
#pragma unroll
    for (int i = 0; i < 2; i++) {
        int g = tid + 256 * i;
        int r = g >> 2, c = g & 3;
        cpasync16(base + r * PITCH + c * 16,
                  (const char*)g_res_h4 + (size_t)(rowBase + r) * 1024 + koff + c * 16);
        cpasync16(base + TILEB + r * PITCH + c * 16,
                  (const char*)g_cb_h4 + (bRow + r) * 1024 + koff + c * 16);
    }
}

__global__ __launch_bounds__(256, 2) void dist_mma_kernel(int qi)
{
    extern __shared__ char smem[];
    uint32_t sb = smem_to_u32(smem);

    const int tid  = threadIdx.x;
    const int wid  = tid >> 5;
    const int lane = tid & 31;
    const int rowBase = blockIdx.x * 128;
    const int wM = (wid & 3) * 32;
    const int wN = (wid >> 2) * 64;

    const int aRow = lane & 15;
    const int aCol = (lane >> 4) * 16;
    const int bRowL = (lane & 7) + ((lane >> 4) << 3);
    const int bColL = ((lane >> 3) & 1) * 16;
    const uint32_t aOffBase = (uint32_t)((wM + aRow) * PITCH + aCol);
    const uint32_t bOffBase = (uint32_t)(TILEB + (wN + bRowL) * PITCH + bColL);

    const float2* csq2 = (const float2*)(g_cbsq + qi * CC);

    float cv1[4], cv2[4], cv3[4], cv4[4];
    int   ci1[4], ci2[4], ci3[4];
#pragma unroll
    for (int s = 0; s < 4; s++) {
        cv1[s] = INFINITY; cv2[s] = INFINITY; cv3[s] = INFINITY; cv4[s] = INFINITY;
        ci1[s] = 0x7fffffff; ci2[s] = 0x7fffffff; ci3[s] = 0x7fffffff;
    }

#pragma unroll 1
    for (int nt = 0; nt < 8; nt++) {
        float acc[2][8][4];
#pragma unroll
        for (int mf = 0; mf < 2; mf++)
#pragma unroll
            for (int nf = 0; nf < 8; nf++)
#pragma unroll
                for (int e = 0; e < 4; e++) acc[mf][nf][e] = 0.f;

        issue_chunk(sb, rowBase, qi, nt, 0, 0); CP_COMMIT();
        issue_chunk(sb, rowBase, qi, nt, 1, 1); CP_COMMIT();
        issue_chunk(sb, rowBase, qi, nt, 2, 2); CP_COMMIT();

#pragma unroll 1
        for (int kc = 0; kc < NKC; kc++) {
            if (kc < NKC - 2) { CP_WAIT(2); } else if (kc == NKC - 2) { CP_WAIT(1); }
            else { CP_WAIT(0); }
            __syncthreads();
            if (kc + 3 < NKC) {
                issue_chunk(sb, rowBase, qi, nt, kc + 3, (kc + 3) & 3);
                CP_COMMIT();
            }

            uint32_t stageBase = sb + (kc & 3) * STAGEB;
#pragma unroll
            for (int k16 = 0; k16 < 2; k16++) {
                uint32_t a[2][4];
#pragma unroll
                for (int mf = 0; mf < 2; mf++)
                    ldsm4(a[mf][0], a[mf][1], a[mf][2], a[mf][3],
                          stageBase + aOffBase + mf * 16 * PITCH + k16 * 32);
#pragma unroll
                for (int np = 0; np < 4; np++) {
                    uint32_t b0, b1, b2, b3;
                    ldsm4(b0, b1, b2, b3,
                          stageBase + bOffBase + np * 16 * PITCH + k16 * 32);
#pragma unroll
                    for (int mf = 0; mf < 2; mf++) {
                        mma16816(acc[mf][np * 2],
                                 a[mf][0], a[mf][1], a[mf][2], a[mf][3], b0, b1);
                        mma16816(acc[mf][np * 2 + 1],
                                 a[mf][0], a[mf][1], a[mf][2], a[mf][3], b2, b3);
                    }
                }
            }
        }
        __syncthreads();

#pragma unroll
        for (int mf = 0; mf < 2; mf++) {
#pragma unroll
            for (int nf = 0; nf < 8; nf++) {
                int n = nt * 128 + wN + nf * 8 + (lane & 3) * 2;
                float2 cq = csq2[n >> 1];
                float v0 = cq.x - 2.f * acc[mf][nf][0];
                float v1 = cq.y - 2.f * acc[mf][nf][1];
                float v2 = cq.x - 2.f * acc[mf][nf][2];
                float v3 = cq.y - 2.f * acc[mf][nf][3];
                int s0 = mf * 2, s1 = mf * 2 + 1;
                ins4(cv1[s0], ci1[s0], cv2[s0], ci2[s0], cv3[s0], ci3[s0], cv4[s0], v0, n);
                ins4(cv1[s0], ci1[s0], cv2[s0], ci2[s0], cv3[s0], ci3[s0], cv4[s0], v1, n + 1);
                ins4(cv1[s1], ci1[s1], cv2[s1], ci2[s1], cv3[s1], ci3[s1], cv4[s1], v2, n);
                ins4(cv1[s1], ci1[s1], cv2[s1], ci2[s1], cv3[s1], ci3[s1], cv4[s1], v3, n + 1);
            }
        }
    }

#pragma unroll
    for (int s = 0; s < 4; s++) {
        int row = rowBase + wM + (s >> 1) * 16 + (s & 1) * 8 + (lane >> 2);
        int contrib = (wid >> 2) * 4 + (lane & 3);
        size_t base = ((size_t)row * 8 + contrib) * 2;
        g_cand[base] = make_uint4(__float_as_uint(cv1[s]), (uint32_t)ci1[s],
                                  __float_as_uint(cv2[s]), (uint32_t)ci2[s]);
        g_cand[base + 1] = make_uint4(__float_as_uint(cv3[s]), (uint32_t)ci3[s],
                                      __float_as_uint(cv4[s]), 0u);
    }
}

// ---------------------------------------------------------------------------
// Exact argmin selection with exact-first thresholding + rotation.
// Warp per row, 4 rows / 128-thread block. No block-level sync.
// ---------------------------------------------------------------------------
__global__ void rotate_kernel(const float* __restrict__ cbs,
                              const float* __restrict__ x, int qi,
                              float* __restrict__ out_q,
                              float* __restrict__ out_if,
                              int writeIdx, int writeLoss, int writeConv)
{
    __shared__ float candV[4][24];
    __shared__ int   candI[4][24];
    __shared__ int   candC[4][24];
    int wslot = threadIdx.x >> 5;
    int row  = blockIdx.x * 4 + (threadIdx.x >> 5);
    int lane = threadIdx.x & 31;
    float* zp = g_residual + (size_t)row * DD;
    const float4* zp4 = (const float4*)zp;

    float zz = g_zz[row];
    float nz = sqrtf(zz);
    float nl = g_nl[row];
    float ncmax = sqrtf(__int_as_float(g_cmaxi[qi]));
    float nlcmax = sqrtf(__int_as_float(g_nlcmaxi[qi]));
    const float* csq = g_cbsq + qi * CC;

    float v1 = INFINITY, v2 = INFINITY, v3 = INFINITY, v4 = INFINITY;
    int i1 = 0x7fffffff, i2 = 0x7fffffff, i3 = 0x7fffffff;
    if (lane < 8) {
        uint4 a = g_cand[((size_t)row * 8 + lane) * 2];
        uint4 b = g_cand[((size_t)row * 8 + lane) * 2 + 1];
        v1 = __uint_as_float(a.x); i1 = (int)a.y;
        v2 = __uint_as_float(a.z); i2 = (int)a.w;
        v3 = __uint_as_float(b.x); i3 = (int)b.y;
        v4 = __uint_as_float(b.z);
    }
    float m = v1;
#pragma unroll
    for (int o = 16; o; o >>= 1) m = fminf(m, __shfl_xor_sync(0xFFFFFFFFu, m, o));
    float w1  = 2.f * (nl * ncmax + (nz + nl) * nlcmax) + 0.1f;  // one-sided bound
    float win = m + 2.f * w1;                                     // two-sided window

    unsigned oflMask = __ballot_sync(0xFFFFFFFFu, v4 <= win);
    int myc = (v1 <= win ? 1 : 0) + (v2 <= win ? 1 : 0) + (v3 <= win ? 1 : 0);
    int tot = myc;
#pragma unroll
    for (int o = 16; o; o >>= 1) tot += __shfl_xor_sync(0xFFFFFFFFu, tot, o);

    bool fast = (oflMask == 0u && tot == 1);
    float4 zv[4];
    int idx;
    if (fast) {
        unsigned bb = __ballot_sync(0xFFFFFFFFu, v1 == m);
        idx = __shfl_sync(0xFFFFFFFFu, i1, __ffs(bb) - 1);
    } else {
        // need z data for exact rescoring
#pragma unroll
        for (int j = 0; j < 4; j++) zv[j] = zp4[lane + 32 * j];

        if (tot <= 24) {
            // gather listed in-window candidates (value + index)
            int off = myc;
#pragma unroll
            for (int o = 1; o < 32; o <<= 1) {
                int t = __shfl_up_sync(0xFFFFFFFFu, off, o);
                if (lane >= o) off += t;
            }
            off -= myc;
            if (lane < 8) {
                int p = off;
                if (v1 <= win) { candV[wslot][p] = v1; candI[wslot][p] = i1; p++; }
                if (v2 <= win) { candV[wslot][p] = v2; candI[wslot][p] = i2; p++; }
                if (v3 <= win) { candV[wslot][p] = v3; candI[wslot][p] = i3; p++; }
            }
            __syncwarp();

            // exact-first: rescore the d~-argmin, derive one-sided threshold
            unsigned bb = __ballot_sync(0xFFFFFFFFu, v1 == m);
            int cstar = __shfl_sync(0xFFFFFFFFu, i1, __ffs(bb) - 1);
            float bd = exact_d(cbs, csq, qi, cstar, zv, lane);
            int bi = cstar;
            float thr = bd + w1;

            // compact survivors (v <= thr, exclude cstar)
            int keep = 0, cidx = 0;
            if (lane < tot) {
                float cvv = candV[wslot][lane];
                cidx = candI[wslot][lane];
                keep = (cvv <= thr && cidx != cstar) ? 1 : 0;
            }
            unsigned km = __ballot_sync(0xFFFFFFFFu, keep);
            if (keep) candC[wslot][__popc(km & ((1u << lane) - 1))] = cidx;
            int tot2 = __popc(km);
            __syncwarp();

            // pipelined exact rescore of survivors (2-deep)
            for (int j = 0; j < tot2; j += 2) {
                int c0 = candC[wslot][j];
                bool has1 = (j + 1 < tot2);
                int c1 = has1 ? candC[wslot][j + 1] : c0;
                const float4* p0 = (const float4*)(cbs + ((size_t)qi * CC + c0) * DD);
                const float4* p1 = (const float4*)(cbs + ((size_t)qi * CC + c1) * DD);
                float s0 = 0.f, s1 = 0.f;
#pragma unroll
                for (int jj = 0; jj < 4; jj++) {
                    float4 q0 = p0[lane + 32 * jj];
                    float4 q1 = p1[lane + 32 * jj];
                    s0 += zv[jj].x*q0.x + zv[jj].y*q0.y + zv[jj].z*q0.z + zv[jj].w*q0.w;
                    s1 += zv[jj].x*q1.x + zv[jj].y*q1.y + zv[jj].z*q1.z + zv[jj].w*q1.w;
                }
#pragma unroll
                for (int o = 16; o; o >>= 1) {
                    s0 += __shfl_xor_sync(0xFFFFFFFFu, s0, o);
                    s1 += __shfl_xor_sync(0xFFFFFFFFu, s1, o);
                }
                float d0 = csq[c0] - 2.f * s0;
                if (d0 < bd || (d0 == bd && c0 < bi)) { bd = d0; bi = c0; }
                if (has1) {
                    float d1 = csq[c1] - 2.f * s1;
                    if (d1 < bd || (d1 == bd && c1 < bi)) { bd = d1; bi = c1; }
                }
            }

            // slot rescans gated on the exact-first threshold (v4 <= bd + w1)
            unsigned om = __ballot_sync(0xFFFFFFFFu, v4 <= bd + w1);
            while (om) {
                int sl = __ffs(om) - 1; om &= om - 1;
                int wNs = (sl >> 2) * 64;
                int l2  = (sl & 3) * 2;
                for (int j = 0; j < 128; j += 2) {
                    int n0 = (j >> 4) * 128 + wNs + ((j >> 1) & 7) * 8 + l2 + (j & 1);
                    int jb = j + 1;
                    int n1 = (jb >> 4) * 128 + wNs + ((jb >> 1) & 7) * 8 + l2 + (jb & 1);
                    const float4* p0 = (const float4*)(cbs + ((size_t)qi * CC + n0) * DD);
                    const float4* p1 = (const float4*)(cbs + ((size_t)qi * CC + n1) * DD);
                    float s0 = 0.f, s1 = 0.f;
#pragma unroll
                    for (int jj = 0; jj < 4; jj++) {
                        float4 q0 = p0[lane + 32 * jj];
                        float4 q1 = p1[lane + 32 * jj];
                        s0 += zv[jj].x*q0.x + zv[jj].y*q0.y + zv[jj].z*q0.z + zv[jj].w*q0.w;
                        s1 += zv[jj].x*q1.x + zv[jj].y*q1.y + zv[jj].z*q1.z + zv[jj].w*q1.w;
                    }
#pragma unroll
                    for (int o = 16; o; o >>= 1) {
                        s0 += __shfl_xor_sync(0xFFFFFFFFu, s0, o);
                        s1 += __shfl_xor_sync(0xFFFFFFFFu, s1, o);
                    }
                    float d0 = csq[n0] - 2.f * s0;
                    float d1 = csq[n1] - 2.f * s1;
                    if (d0 < bd || (d0 == bd && n0 < bi)) { bd = d0; bi = n0; }
                    if (d1 < bd || (d1 == bd && n1 < bi)) { bd = d1; bi = n1; }
                }
            }
            idx = bi;
        } else {
            // extreme fallback: exact full scan
            float bd = INFINITY; int bi = 0x7fffffff;
            for (int c = 0; c < CC; c++) {
                float d = exact_d(cbs, csq, qi, c, zv, lane);
                if (d < bd || (d == bd && c < bi)) { bd = d; bi = c; }
            }
            idx = bi;
        }
    }

    // ---- load q (and z in fast path, overlapped), single zq reduction ----
    const float4* qp4 = (const float4*)(cbs + ((size_t)qi * CC + idx) * DD);
    float4 qv[4];
    if (fast) {
#pragma unroll
        for (int j = 0; j < 4; j++) { zv[j] = zp4[lane + 32 * j]; qv[j] = qp4[lane + 32 * j]; }
    } else {
#pragma unroll
        for (int j = 0; j < 4; j++) qv[j] = qp4[lane + 32 * j];
    }
    float zq = 0.f;
#pragma unroll
    for (int j = 0; j < 4; j++)
        zq += zv[j].x*qv[j].x + zv[j].y*qv[j].y + zv[j].z*qv[j].z + zv[j].w*qv[j].w;
#pragma unroll
    for (int o = 16; o; o >>= 1) zq += __shfl_xor_sync(0xFFFFFFFFu, zq, o);

    float qq = csq[idx];
    float ll = zz - 2.f * zq + qq;

    float nq = sqrtf(qq);
    float iz = 1.f / (nz + EPSF), iq = 1.f / (nq + EPSF);
    float s2 = zz * iz * iz + 2.f * zq * iz * iq + qq * iq * iq;
    float A2 = 2.f * (zz * iz + zq * iq) / s2;
    float Bc = 2.f * zz * iz * iq;
    float cz = 1.f - A2 * iz;
    float cq = Bc - A2 * iq;
    float sc = nq * iz;

    if (writeConv) {
        ushort4* rh = (ushort4*)g_res_h4;
        float nls = 0.f, zz2 = 0.f;
#pragma unroll
        for (int j = 0; j < 4; j++) {
            float4 z = zv[j], q = qv[j], t, r;
            t.x = (z.x * cz + q.x * cq) * sc;
            t.y = (z.y * cz + q.y * cq) * sc;
            t.z = (z.z * cz + q.z * cq) * sc;
            t.w = (z.w * cz + q.w * cq) * sc;
            r.x = z.x - t.x; r.y = z.y - t.y; r.z = z.z - t.z; r.w = z.w - t.w;
            ((float4*)zp)[lane + 32 * j] = r;
            ushort4 h = hi4(r);
            rh[(size_t)row * 128 + lane + 32 * j] = h;
            nls += losq4(r, h);
            zz2 += r.x*r.x + r.y*r.y + r.z*r.z + r.w*r.w;
        }
#pragma unroll
        for (int o = 16; o; o >>= 1) {
            nls += __shfl_xor_sync(0xFFFFFFFFu, nls, o);
            zz2 += __shfl_xor_sync(0xFFFFFFFFu, zz2, o);
        }
        if (lane == 0) { g_nl[row] = sqrtf(nls); g_zz[row] = zz2; }
    } else {
        const float4* xp4 = (const float4*)(x + (size_t)row * DD);
        float4* op4 = (float4*)(out_q + (size_t)row * DD);
#pragma unroll
        for (int j = 0; j < 4; j++) {
            float4 z = zv[j], q = qv[j], t, r, xv;
            t.x = (z.x * cz + q.x * cq) * sc;
            t.y = (z.y * cz + q.y * cq) * sc;
            t.z = (z.z * cz + q.z * cq) * sc;
            t.w = (z.w * cz + q.w * cq) * sc;
            r.x = z.x - t.x; r.y = z.y - t.y; r.z = z.z - t.z; r.w = z.w - t.w;
            xv = xp4[lane + 32 * j];
            op4[lane + 32 * j] = make_float4(xv.x - r.x, xv.y - r.y,
                                             xv.z - r.z, xv.w - r.w);
        }
    }

    if (writeIdx && lane == 0)
        out_if[(size_t)row * BQ + qi] = (float)idx;
    if (writeLoss && lane == 0)
        atomicAdd(&g_loss[qi], ll);
}

// ---------------------------------------------------------------------------
__global__ void final_kernel(float* __restrict__ out_loss) {
    int i = threadIdx.x;
    if (i < BQ) out_loss[i] = g_loss[i] / (float)((size_t)MROWS * DD);
}

// ---------------------------------------------------------------------------
extern "C" void kernel_launch(void* const* d_in, const int* in_sizes, int n_in,
                              void* d_out, int out_size) {
    const float* x   = (const float*)d_in[0];
    const float* cbs = (const float*)d_in[1];
    if (n_in >= 2 && in_sizes[0] == BQ * CC * DD && in_sizes[1] == MROWS * DD) {
        const float* t = x; x = cbs; cbs = t;
    }

    float* out = (float*)d_out;
    const long long qElems = (long long)MROWS * DD;
    const long long iElems = (long long)MROWS * BQ;
    float* out_q = out;
    float* out_i = out + qElems;
    float* out_l = out + qElems + iElems;
    int haveIdx  = (out_size >= qElems + iElems) ? 1 : 0;
    int haveLoss = (out_size >= qElems + iElems + BQ) ? 1 : 0;

    static int attrSet = 0;
    if (!attrSet) {
        cudaFuncSetAttribute(dist_mma_kernel,
                             cudaFuncAttributeMaxDynamicSharedMemorySize, SMEM_DYN);
        attrSet = 1;
    }

    init_kernel<<<MROWS / 8, 256>>>(x);
    cbsq_kernel<<<BQ * CC / 8, 256>>>(cbs);

    for (int qi = 0; qi < BQ; qi++) {
        dist_mma_kernel<<<MROWS / 128, 256, SMEM_DYN>>>(qi);
        rotate_kernel<<<MROWS / 4, 128>>>(cbs, x, qi, out_q, out_i,
                                          haveIdx, haveLoss, qi < BQ - 1);
    }

    if (haveLoss) final_kernel<<<1, 32>>>(out_l);
}

// round 15
// speedup vs baseline: 1.4197x; 1.0794x over previous
#include <cuda_runtime.h>
#include <cuda_fp16.h>
#include <math.h>
#include <stdint.h>

#define BQ 8
#define CC 1024
#define DD 512
#define MROWS 32768            // B*N = 16*2048
#define EPSF 1e-6f

// ---- scratch (device globals; no allocation allowed) ----
__device__ float g_residual[(size_t)MROWS * DD];   // 64 MB fp32 residual
__device__ uint4 g_res_h4[(size_t)MROWS * 64];     // 32 MB fp16 hi  [row][512]
__device__ uint4 g_cb_h4[(size_t)BQ * CC * 64];    // 8 MB fp16 hi codebooks
__device__ float g_cbsq[BQ * CC];
__device__ float g_nl[MROWS];                      // per-row lo-norm ||r - fp16(r)||
__device__ float g_zz[MROWS];                      // per-row ||r||^2
__device__ int   g_cmaxi[BQ];                      // max csq per codebook (bits)
__device__ int   g_nlcmaxi[BQ];                    // max lo-norm^2 per codebook
__device__ float g_loss[BQ];

// ============================================================================
// portable PTX helpers
// ============================================================================
__device__ __forceinline__ uint32_t smem_to_u32(const void* p) {
    uint32_t a;
    asm("{ .reg .u64 t; cvta.to.shared.u64 t, %1; cvt.u32.u64 %0, t; }"
        : "=r"(a) : "l"(p));
    return a;
}
__device__ __forceinline__ void cpasync16(uint32_t dst, const void* src) {
    asm volatile("cp.async.cg.shared.global [%0], [%1], 16;" :: "r"(dst), "l"(src));
}
#define CP_COMMIT() asm volatile("cp.async.commit_group;" ::: "memory")
#define CP_WAIT(n)  asm volatile("cp.async.wait_group %0;" :: "n"(n) : "memory")

__device__ __forceinline__ void ldsm4(uint32_t& r0, uint32_t& r1, uint32_t& r2,
                                      uint32_t& r3, uint32_t addr) {
    asm volatile("ldmatrix.sync.aligned.m8n8.x4.shared.b16 {%0,%1,%2,%3}, [%4];"
                 : "=r"(r0), "=r"(r1), "=r"(r2), "=r"(r3) : "r"(addr));
}
// fp16 MMA, fp32 accumulate
__device__ __forceinline__ void mma16816(float* c, uint32_t a0, uint32_t a1,
                                         uint32_t a2, uint32_t a3,
                                         uint32_t b0, uint32_t b1) {
    asm volatile(
        "mma.sync.aligned.m16n8k16.row.col.f32.f16.f16.f32 "
        "{%0,%1,%2,%3}, {%4,%5,%6,%7}, {%8,%9}, {%0,%1,%2,%3};"
        : "+f"(c[0]), "+f"(c[1]), "+f"(c[2]), "+f"(c[3])
        : "r"(a0), "r"(a1), "r"(a2), "r"(a3), "r"(b0), "r"(b1));
}

__device__ __forceinline__ ushort4 hi4(float4 v) {
    ushort4 h;
    h.x = __half_as_ushort(__float2half_rn(v.x));
    h.y = __half_as_ushort(__float2half_rn(v.y));
    h.z = __half_as_ushort(__float2half_rn(v.z));
    h.w = __half_as_ushort(__float2half_rn(v.w));
    return h;
}
__device__ __forceinline__ float losq4(float4 v, ushort4 h) {
    float dx = v.x - __half2float(__ushort_as_half(h.x));
    float dy = v.y - __half2float(__ushort_as_half(h.y));
    float dz = v.z - __half2float(__ushort_as_half(h.z));
    float dw = v.w - __half2float(__ushort_as_half(h.w));
    return dx*dx + dy*dy + dz*dz + dw*dw;
}

// top-3 + 4th-value sentinel insert
__device__ __forceinline__ void ins4(float& v1, int& i1, float& v2, int& i2,
                                     float& v3, int& i3, float& v4,
                                     float v, int n) {
    if (v < v4) {
        if (v < v1)      { v4 = v3; v3 = v2; i3 = i2; v2 = v1; i2 = i1; v1 = v; i1 = n; }
        else if (v < v2) { v4 = v3; v3 = v2; i3 = i2; v2 = v; i2 = n; }
        else if (v < v3) { v4 = v3; v3 = v; i3 = n; }
        else             { v4 = v; }
    }
}

// warp-cooperative exact distance of row (zv in regs) vs code c
__device__ __forceinline__ float exact_d(const float* __restrict__ cbs,
                                         const float* __restrict__ csq,
                                         int qi, int c, const float4* zv, int lane) {
    const float4* qp4 = (const float4*)(cbs + ((size_t)qi * CC + c) * DD);
    float s = 0.f;
#pragma unroll
    for (int jj = 0; jj < 4; jj++) {
        float4 q = qp4[lane + 32 * jj];
        s += zv[jj].x*q.x + zv[jj].y*q.y + zv[jj].z*q.z + zv[jj].w*q.w;
    }
#pragma unroll
    for (int o = 16; o; o >>= 1) s += __shfl_xor_sync(0xFFFFFFFFu, s, o);
    return csq[c] - 2.f * s;
}

// ---------------------------------------------------------------------------
// init: residual = x (fp32 + fp16 hi), zz + nl per row, reset loss/cmax.
// ---------------------------------------------------------------------------
__global__ void init_kernel(const float* __restrict__ x) {
    int row  = blockIdx.x * 8 + (threadIdx.x >> 5);
    int lane = threadIdx.x & 31;
    const float4* xp = (const float4*)(x + (size_t)row * DD);
    float4* rp = (float4*)(g_residual + (size_t)row * DD);
    ushort4* rh = (ushort4*)g_res_h4;
    float nls = 0.f, zz = 0.f;
#pragma unroll
    for (int j = 0; j < 4; j++) {
        float4 v = xp[lane + 32 * j];
        rp[lane + 32 * j] = v;
        ushort4 h = hi4(v);
        rh[(size_t)row * 128 + lane + 32 * j] = h;
        nls += losq4(v, h);
        zz += v.x*v.x + v.y*v.y + v.z*v.z + v.w*v.w;
    }
#pragma unroll
    for (int o = 16; o; o >>= 1) {
        nls += __shfl_xor_sync(0xFFFFFFFFu, nls, o);
        zz  += __shfl_xor_sync(0xFFFFFFFFu, zz, o);
    }
    if (lane == 0) { g_nl[row] = sqrtf(nls); g_zz[row] = zz; }
    if (blockIdx.x == 0 && threadIdx.x < BQ) {
        g_loss[threadIdx.x] = 0.f;
        g_cmaxi[threadIdx.x] = 0;
        g_nlcmaxi[threadIdx.x] = 0;
    }
}

// ---------------------------------------------------------------------------
// codebook: cb_sq + fp16 hi + per-codebook max csq and max lo-norm^2
// ---------------------------------------------------------------------------
__global__ void cbsq_kernel(const float* __restrict__ cb) {
    int row  = blockIdx.x * 8 + (threadIdx.x >> 5);
    int lane = threadIdx.x & 31;
    const float4* p = (const float4*)(cb + (size_t)row * DD);
    ushort4* ch = (ushort4*)g_cb_h4;
    float s = 0.f, lsq = 0.f;
#pragma unroll
    for (int j = 0; j < 4; j++) {
        float4 v = p[lane + 32 * j];
        s += v.x * v.x + v.y * v.y + v.z * v.z + v.w * v.w;
        ushort4 h = hi4(v);
        ch[(size_t)row * 128 + lane + 32 * j] = h;
        lsq += losq4(v, h);
    }
#pragma unroll
    for (int o = 16; o; o >>= 1) {
        s += __shfl_xor_sync(0xFFFFFFFFu, s, o);
        lsq += __shfl_xor_sync(0xFFFFFFFFu, lsq, o);
    }
    if (lane == 0) {
        g_cbsq[row] = s;
        atomicMax(&g_cmaxi[row >> 10], __float_as_int(s));
        atomicMax(&g_nlcmaxi[row >> 10], __float_as_int(lsq));
    }
}

// ---------------------------------------------------------------------------
// FUSED: hi-only distance GEMM (K=512 fp16) + candidate lists in smem +
// in-kernel exact argmin selection + rotation. Phase 2 runs after the MMA
// phase, reusing the (dead) cp.async stage buffers for candidate storage.
// ---------------------------------------------------------------------------
#define PITCH   80
#define TILEB   (128 * PITCH)
#define STAGEB  (2 * TILEB)
#define NKC     16
#define SMEM_DYN (4 * STAGEB)          // 81920 (cand arrays alias the front)

__device__ __forceinline__ void issue_chunk(
    uint32_t sb, int rowBase, int qi, int nt, int kc, int stage)
{
    int koff = kc * 64;
    uint32_t base = sb + stage * STAGEB;
    int tid = threadIdx.x;
    size_t bRow = (size_t)(qi * CC + nt * 128);
#pragma unroll
    for (int i = 0; i < 2; i++) {
        int g = tid + 256 * i;
        int r = g >> 2, c = g & 3;
        cpasync16(base + r * PITCH + c * 16,
                  (const char*)g_res_h4 + (size_t)(rowBase + r) * 1024 + koff + c * 16);
        cpasync16(base + TILEB + r * PITCH + c * 16,
                  (const char*)g_cb_h4 + (bRow + r) * 1024 + koff + c * 16);
    }
}

__global__ __launch_bounds__(256, 2) void dist_fused_kernel(
    const float* __restrict__ cbs, const float* __restrict__ x, int qi,
    float* __restrict__ out_q, float* __restrict__ out_if,
    int writeIdx, int writeLoss, int writeConv)
{
    extern __shared__ char smem[];
    __shared__ float candV[8][24];
    __shared__ int   candI[8][24];
    __shared__ int   candC[8][24];
    uint32_t sb = smem_to_u32(smem);

    const int tid  = threadIdx.x;
    const int wid  = tid >> 5;
    const int lane = tid & 31;
    const int rowBase = blockIdx.x * 128;
    const int wM = (wid & 3) * 32;
    const int wN = (wid >> 2) * 64;

    const int aRow = lane & 15;
    const int aCol = (lane >> 4) * 16;
    const int bRowL = (lane & 7) + ((lane >> 4) << 3);
    const int bColL = ((lane >> 3) & 1) * 16;
    const uint32_t aOffBase = (uint32_t)((wM + aRow) * PITCH + aCol);
    const uint32_t bOffBase = (uint32_t)(TILEB + (wN + bRowL) * PITCH + bColL);

    const float2* csq2 = (const float2*)(g_cbsq + qi * CC);

    float cv1[4], cv2[4], cv3[4], cv4[4];
    int   ci1[4], ci2[4], ci3[4];
#pragma unroll
    for (int s = 0; s < 4; s++) {
        cv1[s] = INFINITY; cv2[s] = INFINITY; cv3[s] = INFINITY; cv4[s] = INFINITY;
        ci1[s] = 0x7fffffff; ci2[s] = 0x7fffffff; ci3[s] = 0x7fffffff;
    }

    // ===================== Phase 1: MMA + candidate fold ====================
#pragma unroll 1
    for (int nt = 0; nt < 8; nt++) {
        float acc[2][8][4];
#pragma unroll
        for (int mf = 0; mf < 2; mf++)
#pragma unroll
            for (int nf = 0; nf < 8; nf++)
#pragma unroll
                for (int e = 0; e < 4; e++) acc[mf][nf][e] = 0.f;

        issue_chunk(sb, rowBase, qi, nt, 0, 0); CP_COMMIT();
        issue_chunk(sb, rowBase, qi, nt, 1, 1); CP_COMMIT();
        issue_chunk(sb, rowBase, qi, nt, 2, 2); CP_COMMIT();

#pragma unroll 1
        for (int kc = 0; kc < NKC; kc++) {
            if (kc < NKC - 2) { CP_WAIT(2); } else if (kc == NKC - 2) { CP_WAIT(1); }
            else { CP_WAIT(0); }
            __syncthreads();
            if (kc + 3 < NKC) {
                issue_chunk(sb, rowBase, qi, nt, kc + 3, (kc + 3) & 3);
                CP_COMMIT();
            }

            uint32_t stageBase = sb + (kc & 3) * STAGEB;
#pragma unroll
            for (int k16 = 0; k16 < 2; k16++) {
                uint32_t a[2][4];
#pragma unroll
                for (int mf = 0; mf < 2; mf++)
                    ldsm4(a[mf][0], a[mf][1], a[mf][2], a[mf][3],
                          stageBase + aOffBase + mf * 16 * PITCH + k16 * 32);
#pragma unroll
                for (int np = 0; np < 4; np++) {
                    uint32_t b0, b1, b2, b3;
                    ldsm4(b0, b1, b2, b3,
                          stageBase + bOffBase + np * 16 * PITCH + k16 * 32);
#pragma unroll
                    for (int mf = 0; mf < 2; mf++) {
                        mma16816(acc[mf][np * 2],
                                 a[mf][0], a[mf][1], a[mf][2], a[mf][3], b0, b1);
                        mma16816(acc[mf][np * 2 + 1],
                                 a[mf][0], a[mf][1], a[mf][2], a[mf][3], b2, b3);
                    }
                }
            }
        }
        __syncthreads();

#pragma unroll
        for (int mf = 0; mf < 2; mf++) {
#pragma unroll
            for (int nf = 0; nf < 8; nf++) {
                int n = nt * 128 + wN + nf * 8 + (lane & 3) * 2;
                float2 cq = csq2[n >> 1];
                float v0 = cq.x - 2.f * acc[mf][nf][0];
                float v1 = cq.y - 2.f * acc[mf][nf][1];
                float v2 = cq.x - 2.f * acc[mf][nf][2];
                float v3 = cq.y - 2.f * acc[mf][nf][3];
                int s0 = mf * 2, s1 = mf * 2 + 1;
                ins4(cv1[s0], ci1[s0], cv2[s0], ci2[s0], cv3[s0], ci3[s0], cv4[s0], v0, n);
                ins4(cv1[s0], ci1[s0], cv2[s0], ci2[s0], cv3[s0], ci3[s0], cv4[s0], v1, n + 1);
                ins4(cv1[s1], ci1[s1], cv2[s1], ci2[s1], cv3[s1], ci3[s1], cv4[s1], v2, n);
                ins4(cv1[s1], ci1[s1], cv2[s1], ci2[s1], cv3[s1], ci3[s1], cv4[s1], v3, n + 1);
            }
        }
    }

    // dump candidate lists to smem (stage buffers are dead now)
    // layout: sV[row][contrib][4] floats, sIx[row][contrib][4] ints
    float* sV  = (float*)smem;                   // 128*8*4*4 = 16384 B
    int*   sIx = (int*)(smem + 16384);           // 16384 B
    __syncthreads();
#pragma unroll
    for (int s = 0; s < 4; s++) {
        int rowLocal = wM + (s >> 1) * 16 + (s & 1) * 8 + (lane >> 2);
        int contrib = (wid >> 2) * 4 + (lane & 3);
        int base = (rowLocal * 8 + contrib) * 4;
        sV[base + 0] = cv1[s]; sV[base + 1] = cv2[s];
        sV[base + 2] = cv3[s]; sV[base + 3] = cv4[s];
        sIx[base + 0] = ci1[s]; sIx[base + 1] = ci2[s]; sIx[base + 2] = ci3[s];
    }
    __syncthreads();

    // ============ Phase 2: selection + rotation (warp w: 16 rows) ===========
    float ncmax = sqrtf(__int_as_float(g_cmaxi[qi]));
    float nlcmax = sqrtf(__int_as_float(g_nlcmaxi[qi]));
    const float* csq = g_cbsq + qi * CC;

#pragma unroll 1
    for (int k = 0; k < 16; k++) {
        int rowLocal = wid * 16 + k;
        int row = rowBase + rowLocal;
        float* zp = g_residual + (size_t)row * DD;
        const float4* zp4 = (const float4*)zp;

        float zz = g_zz[row];
        float nz = sqrtf(zz);
        float nl = g_nl[row];

        float v1 = INFINITY, v2 = INFINITY, v3 = INFINITY, v4 = INFINITY;
        int i1 = 0x7fffffff, i2 = 0x7fffffff, i3 = 0x7fffffff;
        if (lane < 8) {
            int base = (rowLocal * 8 + lane) * 4;
            v1 = sV[base + 0]; v2 = sV[base + 1];
            v3 = sV[base + 2]; v4 = sV[base + 3];
            i1 = sIx[base + 0]; i2 = sIx[base + 1]; i3 = sIx[base + 2];
        }
        float m = v1;
#pragma unroll
        for (int o = 16; o; o >>= 1) m = fminf(m, __shfl_xor_sync(0xFFFFFFFFu, m, o));
        float w1  = 2.f * (nl * ncmax + (nz + nl) * nlcmax) + 0.1f;
        float win = m + 2.f * w1;

        unsigned oflMask = __ballot_sync(0xFFFFFFFFu, v4 <= win);
        int myc = (v1 <= win ? 1 : 0) + (v2 <= win ? 1 : 0) + (v3 <= win ? 1 : 0);
        int tot = myc;
#pragma unroll
        for (int o = 16; o; o >>= 1) tot += __shfl_xor_sync(0xFFFFFFFFu, tot, o);

        bool fast = (oflMask == 0u && tot == 1);
        float4 zv[4];
        int idx;
        if (fast) {
            unsigned bb = __ballot_sync(0xFFFFFFFFu, v1 == m);
            idx = __shfl_sync(0xFFFFFFFFu, i1, __ffs(bb) - 1);
        } else {
#pragma unroll
            for (int j = 0; j < 4; j++) zv[j] = zp4[lane + 32 * j];

            if (tot <= 24) {
                int off = myc;
#pragma unroll
                for (int o = 1; o < 32; o <<= 1) {
                    int t = __shfl_up_sync(0xFFFFFFFFu, off, o);
                    if (lane >= o) off += t;
                }
                off -= myc;
                if (lane < 8) {
                    int p = off;
                    if (v1 <= win) { candV[wid][p] = v1; candI[wid][p] = i1; p++; }
                    if (v2 <= win) { candV[wid][p] = v2; candI[wid][p] = i2; p++; }
                    if (v3 <= win) { candV[wid][p] = v3; candI[wid][p] = i3; p++; }
                }
                __syncwarp();

                // exact-first: rescore the d~-argmin, derive one-sided threshold
                unsigned bb = __ballot_sync(0xFFFFFFFFu, v1 == m);
                int cstar = __shfl_sync(0xFFFFFFFFu, i1, __ffs(bb) - 1);
                float bd = exact_d(cbs, csq, qi, cstar, zv, lane);
                int bi = cstar;
                float thr = bd + w1;

                int keep = 0, cidx = 0;
                if (lane < tot) {
                    float cvv = candV[wid][lane];
                    cidx = candI[wid][lane];
                    keep = (cvv <= thr && cidx != cstar) ? 1 : 0;
                }
                unsigned km = __ballot_sync(0xFFFFFFFFu, keep);
                if (keep) candC[wid][__popc(km & ((1u << lane) - 1))] = cidx;
                int tot2 = __popc(km);
                __syncwarp();

                for (int j = 0; j < tot2; j += 2) {
                    int c0 = candC[wid][j];
                    bool has1 = (j + 1 < tot2);
                    int c1 = has1 ? candC[wid][j + 1] : c0;
                    const float4* p0 = (const float4*)(cbs + ((size_t)qi * CC + c0) * DD);
                    const float4* p1 = (const float4*)(cbs + ((size_t)qi * CC + c1) * DD);
                    float s0 = 0.f, s1 = 0.f;
#pragma unroll
                    for (int jj = 0; jj < 4; jj++) {
                        float4 q0 = p0[lane + 32 * jj];
                        float4 q1 = p1[lane + 32 * jj];
                        s0 += zv[jj].x*q0.x + zv[jj].y*q0.y + zv[jj].z*q0.z + zv[jj].w*q0.w;
                        s1 += zv[jj].x*q1.x + zv[jj].y*q1.y + zv[jj].z*q1.z + zv[jj].w*q1.w;
                    }
#pragma unroll
                    for (int o = 16; o; o >>= 1) {
                        s0 += __shfl_xor_sync(0xFFFFFFFFu, s0, o);
                        s1 += __shfl_xor_sync(0xFFFFFFFFu, s1, o);
                    }
                    float d0 = csq[c0] - 2.f * s0;
                    if (d0 < bd || (d0 == bd && c0 < bi)) { bd = d0; bi = c0; }
                    if (has1) {
                        float d1 = csq[c1] - 2.f * s1;
                        if (d1 < bd || (d1 == bd && c1 < bi)) { bd = d1; bi = c1; }
                    }
                }

                unsigned om = __ballot_sync(0xFFFFFFFFu, v4 <= bd + w1);
                while (om) {
                    int sl = __ffs(om) - 1; om &= om - 1;
                    int wNs = (sl >> 2) * 64;
                    int l2  = (sl & 3) * 2;
                    for (int j = 0; j < 128; j += 2) {
                        int n0 = (j >> 4) * 128 + wNs + ((j >> 1) & 7) * 8 + l2 + (j & 1);
                        int jb = j + 1;
                        int n1 = (jb >> 4) * 128 + wNs + ((jb >> 1) & 7) * 8 + l2 + (jb & 1);
                        const float4* p0 = (const float4*)(cbs + ((size_t)qi * CC + n0) * DD);
                        const float4* p1 = (const float4*)(cbs + ((size_t)qi * CC + n1) * DD);
                        float s0 = 0.f, s1 = 0.f;
#pragma unroll
                        for (int jj = 0; jj < 4; jj++) {
                            float4 q0 = p0[lane + 32 * jj];
                            float4 q1 = p1[lane + 32 * jj];
                            s0 += zv[jj].x*q0.x + zv[jj].y*q0.y + zv[jj].z*q0.z + zv[jj].w*q0.w;
                            s1 += zv[jj].x*q1.x + zv[jj].y*q1.y + zv[jj].z*q1.z + zv[jj].w*q1.w;
                        }
#pragma unroll
                        for (int o = 16; o; o >>= 1) {
                            s0 += __shfl_xor_sync(0xFFFFFFFFu, s0, o);
                            s1 += __shfl_xor_sync(0xFFFFFFFFu, s1, o);
                        }
                        float d0 = csq[n0] - 2.f * s0;
                        float d1 = csq[n1] - 2.f * s1;
                        if (d0 < bd || (d0 == bd && n0 < bi)) { bd = d0; bi = n0; }
                        if (d1 < bd || (d1 == bd && n1 < bi)) { bd = d1; bi = n1; }
                    }
                }
                idx = bi;
            } else {
                float bd = INFINITY; int bi = 0x7fffffff;
                for (int c = 0; c < CC; c++) {
                    float d = exact_d(cbs, csq, qi, c, zv, lane);
                    if (d < bd || (d == bd && c < bi)) { bd = d; bi = c; }
                }
                idx = bi;
            }
        }

        // ---- rotation ----
        const float4* qp4 = (const float4*)(cbs + ((size_t)qi * CC + idx) * DD);
        float4 qv[4];
        if (fast) {
#pragma unroll
            for (int j = 0; j < 4; j++) { zv[j] = zp4[lane + 32 * j]; qv[j] = qp4[lane + 32 * j]; }
        } else {
#pragma unroll
            for (int j = 0; j < 4; j++) qv[j] = qp4[lane + 32 * j];
        }
        float zq = 0.f;
#pragma unroll
        for (int j = 0; j < 4; j++)
            zq += zv[j].x*qv[j].x + zv[j].y*qv[j].y + zv[j].z*qv[j].z + zv[j].w*qv[j].w;
#pragma unroll
        for (int o = 16; o; o >>= 1) zq += __shfl_xor_sync(0xFFFFFFFFu, zq, o);

        float qq = csq[idx];
        float ll = zz - 2.f * zq + qq;

        float nq = sqrtf(qq);
        float iz = 1.f / (nz + EPSF), iq = 1.f / (nq + EPSF);
        float s2 = zz * iz * iz + 2.f * zq * iz * iq + qq * iq * iq;
        float A2 = 2.f * (zz * iz + zq * iq) / s2;
        float Bc = 2.f * zz * iz * iq;
        float cz = 1.f - A2 * iz;
        float cq = Bc - A2 * iq;
        float sc = nq * iz;

        if (writeConv) {
            ushort4* rh = (ushort4*)g_res_h4;
            float nls = 0.f, zz2 = 0.f;
#pragma unroll
            for (int j = 0; j < 4; j++) {
                float4 z = zv[j], q = qv[j], t, r;
                t.x = (z.x * cz + q.x * cq) * sc;
                t.y = (z.y * cz + q.y * cq) * sc;
                t.z = (z.z * cz + q.z * cq) * sc;
                t.w = (z.w * cz + q.w * cq) * sc;
                r.x = z.x - t.x; r.y = z.y - t.y; r.z = z.z - t.z; r.w = z.w - t.w;
                ((float4*)zp)[lane + 32 * j] = r;
                ushort4 h = hi4(r);
                rh[(size_t)row * 128 + lane + 32 * j] = h;
                nls += losq4(r, h);
                zz2 += r.x*r.x + r.y*r.y + r.z*r.z + r.w*r.w;
            }
#pragma unroll
            for (int o = 16; o; o >>= 1) {
                nls += __shfl_xor_sync(0xFFFFFFFFu, nls, o);
                zz2 += __shfl_xor_sync(0xFFFFFFFFu, zz2, o);
            }
            if (lane == 0) { g_nl[row] = sqrtf(nls); g_zz[row] = zz2; }
        } else {
            const float4* xp4 = (const float4*)(x + (size_t)row * DD);
            float4* op4 = (float4*)(out_q + (size_t)row * DD);
#pragma unroll
            for (int j = 0; j < 4; j++) {
                float4 z = zv[j], q = qv[j], t, r, xv;
                t.x = (z.x * cz + q.x * cq) * sc;
                t.y = (z.y * cz + q.y * cq) * sc;
                t.z = (z.z * cz + q.z * cq) * sc;
                t.w = (z.w * cz + q.w * cq) * sc;
                r.x = z.x - t.x; r.y = z.y - t.y; r.z = z.z - t.z; r.w = z.w - t.w;
                xv = xp4[lane + 32 * j];
                op4[lane + 32 * j] = make_float4(xv.x - r.x, xv.y - r.y,
                                                 xv.z - r.z, xv.w - r.w);
            }
        }

        if (writeIdx && lane == 0)
            out_if[(size_t)row * BQ + qi] = (float)idx;
        if (writeLoss && lane == 0)
            atomicAdd(&g_loss[qi], ll);
    }
}

// ---------------------------------------------------------------------------
__global__ void final_kernel(float* __restrict__ out_loss) {
    int i = threadIdx.x;
    if (i < BQ) out_loss[i] = g_loss[i] / (float)((size_t)MROWS * DD);
}

// ---------------------------------------------------------------------------
extern "C" void kernel_launch(void* const* d_in, const int* in_sizes, int n_in,
                              void* d_out, int out_size) {
    const float* x   = (const float*)d_in[0];
    const float* cbs = (const float*)d_in[1];
    if (n_in >= 2 && in_sizes[0] == BQ * CC * DD && in_sizes[1] == MROWS * DD) {
        const float* t = x; x = cbs; cbs = t;
    }

    float* out = (float*)d_out;
    const long long qElems = (long long)MROWS * DD;
    const long long iElems = (long long)MROWS * BQ;
    float* out_q = out;
    float* out_i = out + qElems;
    float* out_l = out + qElems + iElems;
    int haveIdx  = (out_size >= qElems + iElems) ? 1 : 0;
    int haveLoss = (out_size >= qElems + iElems + BQ) ? 1 : 0;

    static int attrSet = 0;
    if (!attrSet) {
        cudaFuncSetAttribute(dist_fused_kernel,
                             cudaFuncAttributeMaxDynamicSharedMemorySize, SMEM_DYN);
        attrSet = 1;
    }

    init_kernel<<<MROWS / 8, 256>>>(x);
    cbsq_kernel<<<BQ * CC / 8, 256>>>(cbs);

    for (int qi = 0; qi < BQ; qi++) {
        dist_fused_kernel<<<MROWS / 128, 256, SMEM_DYN>>>(
            cbs, x, qi, out_q, out_i, haveIdx, haveLoss, qi < BQ - 1);
    }

    if (haveLoss) final_kernel<<<1, 32>>>(out_l);
}